// round 6
// baseline (speedup 1.0000x reference)
#include <cuda_runtime.h>
#include <cuda_bf16.h>
#include <cstdint>

#define BB 2
#define LL 1024
#define DM 768
#define DI 1536
#define DS 16
#define DTR 48
#define XD 80            // DT_RANK + 2*D_STATE
#define NL 6
#define VOCAB_N 32000
#define DE 384
#define TOK (BB*LL)      // 2048
#define CH 8             // scan chunks
#define CLEN 128         // steps per chunk
#define DTKP 160         // padded K3 for dt projection (144 -> 160)

typedef __nv_bfloat16 bf16;

// ------------------------- scratch (no allocation allowed) -------------------
__device__ __align__(128) float g_hidden[TOK*DM];
__device__ __align__(128) float g_residual[TOK*DM];
__device__ __align__(128) float g_hs[TOK*DM];
__device__ __align__(128) float g_xz[TOK*2*DI];
__device__ __align__(128) float g_xconv[TOK*DI];
__device__ __align__(128) float g_xdbl[TOK*XD];
__device__ __align__(128) float g_dt[TOK*DI];
__device__ __align__(128) bf16  g_ab[TOK*3*DI];        // split3 activations
__device__ __align__(128) bf16  g_wb[VOCAB_N*3*DE];    // split3 weights
__device__ __align__(128) float g_P[BB*DI*CH*DS];      // scan chunk decay products
__device__ __align__(128) float g_S[BB*DI*CH*DS];      // scan chunk partial states
__device__ __align__(128) float g_hin[BB*DI*CH*DS];    // scan chunk input states

// ------------------------- embed ---------------------------------------------
__global__ void embed_kernel(const int* __restrict__ ids, const int* __restrict__ pos,
                             const float* __restrict__ emb, const float* __restrict__ pemb,
                             float* __restrict__ hidden, float* __restrict__ res)
{
    int idx = blockIdx.x * blockDim.x + threadIdx.x;
    if (idx >= TOK*DM) return;
    int t = idx / DM, c = idx % DM;
    float v;
    if (c < DE) v = emb[(size_t)ids[t]*DE + c];
    else        v = pemb[(size_t)pos[t]*DE + (c-DE)];
    hidden[idx] = v;
    res[idx] = 0.f;
}

__global__ void zero_kernel(float* __restrict__ p, int n)
{
    int i = blockIdx.x * blockDim.x + threadIdx.x;
    if (i < n) p[i] = 0.f;
}

// ---------------- split3 helpers ---------------------------------------------
// A row (stride 3K): [hi | lo | hi] ; B row (stride 3K): [hi | hi | lo]
__device__ __forceinline__ void splitA_write(bf16* row, int K, int k, float v)
{
    bf16 hi = __float2bfloat16(v);
    row[k] = hi;
    row[2*K + k] = hi;
    row[K + k] = __float2bfloat16(v - __bfloat162float(hi));
}
__device__ __forceinline__ void splitB_write(bf16* row, int K, int k, float v)
{
    bf16 hi = __float2bfloat16(v);
    row[k] = hi;
    row[K + k] = hi;
    row[2*K + k] = __float2bfloat16(v - __bfloat162float(hi));
}

__global__ void split3A_kernel(const float* __restrict__ src, int lda, int K, int total,
                               bf16* __restrict__ dst)
{
    int idx = blockIdx.x * blockDim.x + threadIdx.x;
    if (idx >= total) return;
    int m = idx / K, k = idx - m*K;
    splitA_write(dst + (size_t)m*(3*K), K, k, src[(size_t)m*lda + k]);
}
__global__ void split3B_kernel(const float* __restrict__ src, int lda, int K, int total,
                               bf16* __restrict__ dst)
{
    int idx = blockIdx.x * blockDim.x + threadIdx.x;
    if (idx >= total) return;
    int m = idx / K, k = idx - m*K;
    splitB_write(dst + (size_t)m*(3*K), K, k, src[(size_t)m*lda + k]);
}

// dt splits: K=48 -> row stride DTKP (=160), entries 144..159 zero-padded
__global__ void split3A_dt_kernel(const float* __restrict__ src, int total,
                                  bf16* __restrict__ dst)
{
    int idx = blockIdx.x * blockDim.x + threadIdx.x;   // over M*64
    if (idx >= total) return;
    int m = idx >> 6, k = idx & 63;
    bf16* row = dst + (size_t)m*DTKP;
    if (k < DTR) splitA_write(row, DTR, k, src[(size_t)m*XD + k]);
    else         row[96 + k] = __float2bfloat16(0.f);  // 144..159
}
__global__ void split3B_dt_kernel(const float* __restrict__ src, int total,
                                  bf16* __restrict__ dst)
{
    int idx = blockIdx.x * blockDim.x + threadIdx.x;   // over N*64
    if (idx >= total) return;
    int m = idx >> 6, k = idx & 63;
    bf16* row = dst + (size_t)m*DTKP;
    if (k < DTR) splitB_write(row, DTR, k, src[(size_t)m*DTR + k]);
    else         row[96 + k] = __float2bfloat16(0.f);
}

// ---- fused: res += hidden ; out = rmsnorm(res)*w ; + split3A output ---------
__global__ __launch_bounds__(256) void addnorm_kernel(
    const float* __restrict__ h, float* __restrict__ res,
    const float* __restrict__ w, float* __restrict__ out, bf16* __restrict__ outs)
{
    int t = blockIdx.x;
    const float* hp = h + (size_t)t*DM;
    float* rp = res + (size_t)t*DM;
    float v[3];
    float ss = 0.f;
#pragma unroll
    for (int q = 0; q < 3; q++) {
        int i = threadIdx.x + q*256;
        v[q] = hp[i] + rp[i];
        ss += v[q]*v[q];
    }
#pragma unroll
    for (int o = 16; o > 0; o >>= 1) ss += __shfl_xor_sync(0xffffffffu, ss, o);
    __shared__ float red[8];
    if ((threadIdx.x & 31) == 0) red[threadIdx.x >> 5] = ss;
    __syncthreads();
    float tot = 0.f;
#pragma unroll
    for (int q = 0; q < 8; q++) tot += red[q];
    float rstd = rsqrtf(tot * (1.f/(float)DM) + 1e-5f);
    bf16* orow = outs + (size_t)t*(3*DM);
#pragma unroll
    for (int q = 0; q < 3; q++) {
        int i = threadIdx.x + q*256;
        rp[i] = v[q];
        float u = v[q] * rstd * w[i];
        out[(size_t)t*DM + i] = u;
        splitA_write(orow, DM, i, u);
    }
}

// ---- depthwise causal conv (width 4) + bias + silu (+split3A output) -------
__global__ void conv_silu_kernel(const float* __restrict__ xz,
                                 const float* __restrict__ cw,
                                 const float* __restrict__ cb,
                                 float* __restrict__ out, bf16* __restrict__ outs)
{
    int idx = blockIdx.x * blockDim.x + threadIdx.x;
    if (idx >= TOK*DI) return;
    int d = idx % DI;
    int t = idx / DI;
    int l = t % LL;
    float acc = cb[d];
    const float* base = xz + (size_t)t*(2*DI) + d;
#pragma unroll
    for (int j = 0; j < 4; j++) {
        int ll = l - 3 + j;
        if (ll >= 0) acc += cw[d*4+j] * base[(j-3)*(2*DI)];
    }
    float v = acc / (1.f + __expf(-acc));
    out[idx] = v;
    splitA_write(outs + (size_t)t*(3*DI), DI, d, v);
}

// ---------------- chunked selective scan -------------------------------------
__global__ __launch_bounds__(256) void scanA_kernel(
    const float* __restrict__ xc, const float* __restrict__ dt,
    const float* __restrict__ xd, const float* __restrict__ A_log,
    float* __restrict__ Pv, float* __restrict__ Sv)
{
    int tid = threadIdx.x;
    int u = blockIdx.x * 16 + (tid >> 4);   // (pair, chunk)
    int n = tid & 15;
    int p = u >> 3;                          // CH=8
    int c = u & 7;
    int b = p / DI, d = p - b*DI;
    float A = -__expf(A_log[d*DS + n]);
    const float* xcb = xc + (size_t)b*LL*DI + d;
    const float* dtb = dt + (size_t)b*LL*DI + d;
    const float* xdb = xd + (size_t)b*LL*XD + DTR + n;
    int l0 = c * CLEN;
    float P = 1.f, h = 0.f;
#pragma unroll 4
    for (int i = 0; i < CLEN; i++) {
        int l = l0 + i;
        float xv  = xcb[(size_t)l*DI];
        float dtv = dtb[(size_t)l*DI];
        float Bv  = xdb[(size_t)l*XD];
        float dA  = __expf(dtv * A);
        P *= dA;
        h = dA*h + (dtv*xv)*Bv;
    }
    Pv[(size_t)u*DS + n] = P;
    Sv[(size_t)u*DS + n] = h;
}

__global__ void scanB_kernel(const float* __restrict__ Pv, const float* __restrict__ Sv,
                             float* __restrict__ hin)
{
    int g = blockIdx.x * blockDim.x + threadIdx.x;   // p*DS + n
    if (g >= BB*DI*DS) return;
    int p = g / DS, n = g - p*DS;
    float h = 0.f;
#pragma unroll
    for (int c = 0; c < CH; c++) {
        size_t idx = ((size_t)p*CH + c)*DS + n;
        hin[idx] = h;
        h = Pv[idx]*h + Sv[idx];
    }
}

__global__ __launch_bounds__(256) void scanC_kernel(
    const float* __restrict__ xc, const float* __restrict__ dt,
    const float* __restrict__ xd, const float* __restrict__ xz,
    const float* __restrict__ A_log, const float* __restrict__ Dv,
    const float* __restrict__ hin, bf16* __restrict__ ys)
{
    int tid = threadIdx.x;
    int u = blockIdx.x * 16 + (tid >> 4);
    int n = tid & 15;
    int p = u >> 3;
    int c = u & 7;
    int b = p / DI, d = p - b*DI;
    float A = -__expf(A_log[d*DS + n]);
    float Dval = Dv[d];
    const float* xcb = xc + (size_t)b*LL*DI + d;
    const float* dtb = dt + (size_t)b*LL*DI + d;
    const float* xdb = xd + (size_t)b*LL*XD + DTR + n;
    const float* xzb = xz + (size_t)b*LL*(2*DI) + DI + d;
    bf16* yb = ys + (size_t)b*LL*(3*DI);
    int l0 = c * CLEN;
    float h = hin[(size_t)u*DS + n];
#pragma unroll 4
    for (int i = 0; i < CLEN; i++) {
        int l = l0 + i;
        float xv  = xcb[(size_t)l*DI];
        float dtv = dtb[(size_t)l*DI];
        float Bv  = xdb[(size_t)l*XD];
        float Cv  = xdb[(size_t)l*XD + DS];
        float dA  = __expf(dtv * A);
        h = dA*h + (dtv*xv)*Bv;
        float part = h*Cv;
        part += __shfl_xor_sync(0xffffffffu, part, 1);
        part += __shfl_xor_sync(0xffffffffu, part, 2);
        part += __shfl_xor_sync(0xffffffffu, part, 4);
        part += __shfl_xor_sync(0xffffffffu, part, 8);
        if (n == 0) {
            float z = xzb[(size_t)l*(2*DI)];
            float sig = 1.f / (1.f + __expf(-z));
            float v = (part + xv*Dval) * (z * sig);
            splitA_write(yb + (size_t)l*(3*DI), DI, d, v);
        }
    }
}

// --------------------------- tensor-core GEMM --------------------------------
// C[m,n] = sum_k A[m,k]*B[n,k]. 128x128 block, BK=32, 4-stage cp.async pipeline.
__device__ __forceinline__ void ldsm_x4(uint32_t* r, uint32_t addr){
    asm volatile("ldmatrix.sync.aligned.m8n8.x4.shared.b16 {%0,%1,%2,%3}, [%4];"
      : "=r"(r[0]),"=r"(r[1]),"=r"(r[2]),"=r"(r[3]) : "r"(addr));
}
__device__ __forceinline__ void mma_bf16(float* c, const uint32_t* a, const uint32_t* b){
    asm volatile("mma.sync.aligned.m16n8k16.row.col.f32.bf16.bf16.f32 "
      "{%0,%1,%2,%3}, {%4,%5,%6,%7}, {%8,%9}, {%0,%1,%2,%3};"
      : "+f"(c[0]),"+f"(c[1]),"+f"(c[2]),"+f"(c[3])
      : "r"(a[0]),"r"(a[1]),"r"(a[2]),"r"(a[3]), "r"(b[0]),"r"(b[1]));
}
__device__ __forceinline__ void cp16(uint32_t daddr, const void* gptr, uint32_t srcsz){
    asm volatile("cp.async.cg.shared.global [%0], [%1], 16, %2;\n"
      :: "r"(daddr), "l"(gptr), "r"(srcsz));
}

#define SSTRIDE 40
#define STAGE_ELEM (128*SSTRIDE)           // bf16 elems per matrix per stage
#define STAGE_BYTES (STAGE_ELEM*2)         // 10240 B
#define NSTAGE 4
#define GEMM_SMEM (NSTAGE*2*STAGE_BYTES)   // 81920 B

__global__ __launch_bounds__(256,2) void gemm_mma(
    const bf16* __restrict__ A, const bf16* __restrict__ B,
    float* __restrict__ C, int N, int K2, int ldc,
    int katomic, int epi, const float* __restrict__ bias)
{
    extern __shared__ __align__(16) bf16 smem[];
    const int tid = threadIdx.x;
    const int lane = tid & 31, wid = tid >> 5;
    const int wm = wid & 1, wn = wid >> 1;
    const int bm = blockIdx.x * 128, bn = blockIdx.y * 128;

    const int ksplit = gridDim.z;
    const int per = (K2 / 32) / ksplit;
    const int kbeg = blockIdx.z * per * 32;
    const int iters = per;

    // 16B chunk mapping: 2 chunks per matrix per thread
    const int r0 = tid >> 2,            c0 = (tid & 3) * 8;
    const int r1 = (tid + 256) >> 2,    c1 = ((tid + 256) & 3) * 8;

    uint32_t sbase = (uint32_t)__cvta_generic_to_shared(smem);

    const int bw0 = bn + r0, bw1 = bn + r1;
    const bool bv0 = bw0 < N, bv1 = bw1 < N;
    const bf16* Bq0 = B + (size_t)(bv0 ? bw0 : 0)*K2;
    const bf16* Bq1 = B + (size_t)(bv1 ? bw1 : 0)*K2;
    const bf16* Aq0 = A + (size_t)(bm + r0)*K2;
    const bf16* Aq1 = A + (size_t)(bm + r1)*K2;

    const uint32_t aoff0 = (uint32_t)(r0*SSTRIDE + c0)*2;
    const uint32_t aoff1 = (uint32_t)(r1*SSTRIDE + c1)*2;

    float acc[4][4][4];
#pragma unroll
    for (int i = 0; i < 4; i++)
#pragma unroll
        for (int j = 0; j < 4; j++)
#pragma unroll
            for (int q = 0; q < 4; q++) acc[i][j][q] = 0.f;

    // prologue: stages 0..2
#pragma unroll
    for (int s = 0; s < NSTAGE-1; s++) {
        if (s < iters) {
            int k = kbeg + s*32;
            uint32_t sA = sbase + (uint32_t)s*STAGE_BYTES;
            uint32_t sB = sbase + (uint32_t)(NSTAGE + s)*STAGE_BYTES;
            cp16(sA + aoff0, Aq0 + k + c0, 16u);
            cp16(sA + aoff1, Aq1 + k + c1, 16u);
            cp16(sB + aoff0, Bq0 + k + c0, bv0 ? 16u : 0u);
            cp16(sB + aoff1, Bq1 + k + c1, bv1 ? 16u : 0u);
        }
        asm volatile("cp.async.commit_group;\n" ::: "memory");
    }

    const int ar  = lane & 15;
    const int ak  = (lane >> 4) * 8;
    const int brr = (lane & 7) + ((lane >> 4) & 1)*8;
    const int bk  = ((lane >> 3) & 1) * 8;

    for (int it = 0; it < iters; it++) {
        int rem = iters - 1 - it;
        if (rem >= 2)      { asm volatile("cp.async.wait_group 2;\n" ::: "memory"); }
        else if (rem == 1) { asm volatile("cp.async.wait_group 1;\n" ::: "memory"); }
        else               { asm volatile("cp.async.wait_group 0;\n" ::: "memory"); }
        __syncthreads();

        // issue stage it+3 into freed buffer
        {
            int s = it + NSTAGE - 1;
            if (s < iters) {
                int k = kbeg + s*32;
                int bufn = s & (NSTAGE-1);
                uint32_t sA = sbase + (uint32_t)bufn*STAGE_BYTES;
                uint32_t sB = sbase + (uint32_t)(NSTAGE + bufn)*STAGE_BYTES;
                cp16(sA + aoff0, Aq0 + k + c0, 16u);
                cp16(sA + aoff1, Aq1 + k + c1, 16u);
                cp16(sB + aoff0, Bq0 + k + c0, bv0 ? 16u : 0u);
                cp16(sB + aoff1, Bq1 + k + c1, bv1 ? 16u : 0u);
                asm volatile("cp.async.commit_group;\n" ::: "memory");
            }
        }

        int buf = it & (NSTAGE-1);
        uint32_t sAc = sbase + (uint32_t)buf*STAGE_BYTES;
        uint32_t sBc = sbase + (uint32_t)(NSTAGE + buf)*STAGE_BYTES;
#pragma unroll
        for (int kk = 0; kk < 2; kk++) {
            uint32_t afr[4][4], bfr[4][2];
#pragma unroll
            for (int mi = 0; mi < 4; mi++) {
                int row = wm*64 + mi*16 + ar;
                ldsm_x4(afr[mi], sAc + (uint32_t)(row*SSTRIDE + kk*16 + ak)*2);
            }
#pragma unroll
            for (int np = 0; np < 2; np++) {
                int row = wn*32 + np*16 + brr;
                uint32_t q4[4];
                ldsm_x4(q4, sBc + (uint32_t)(row*SSTRIDE + kk*16 + bk)*2);
                bfr[np*2+0][0]=q4[0]; bfr[np*2+0][1]=q4[1];
                bfr[np*2+1][0]=q4[2]; bfr[np*2+1][1]=q4[3];
            }
#pragma unroll
            for (int mi = 0; mi < 4; mi++)
#pragma unroll
                for (int ni = 0; ni < 4; ni++)
                    mma_bf16(acc[mi][ni], afr[mi], bfr[ni]);
        }
    }

    const int grp = lane >> 2, qd = lane & 3;
#pragma unroll
    for (int mi = 0; mi < 4; mi++) {
        int m = bm + wm*64 + mi*16 + grp;
#pragma unroll
        for (int ni = 0; ni < 4; ni++) {
            int n = bn + wn*32 + ni*8 + qd*2;
            if (n < N) {
                float c0v = acc[mi][ni][0], c1v = acc[mi][ni][1];
                float c2v = acc[mi][ni][2], c3v = acc[mi][ni][3];
                if (epi == 1) {
                    float b0 = bias[n], b1 = bias[n+1];
                    float x0 = c0v + b0, x1 = c1v + b1, x2 = c2v + b0, x3 = c3v + b1;
                    c0v = (x0 > 20.f) ? x0 : log1pf(__expf(x0));
                    c1v = (x1 > 20.f) ? x1 : log1pf(__expf(x1));
                    c2v = (x2 > 20.f) ? x2 : log1pf(__expf(x2));
                    c3v = (x3 > 20.f) ? x3 : log1pf(__expf(x3));
                }
                if (katomic) {
                    atomicAdd(&C[(size_t)m*ldc + n],       c0v);
                    if (n+1 < N) atomicAdd(&C[(size_t)m*ldc + n+1], c1v);
                    atomicAdd(&C[(size_t)(m+8)*ldc + n],   c2v);
                    if (n+1 < N) atomicAdd(&C[(size_t)(m+8)*ldc + n+1], c3v);
                } else {
                    *(float2*)(&C[(size_t)m*ldc + n])     = make_float2(c0v, c1v);
                    *(float2*)(&C[(size_t)(m+8)*ldc + n]) = make_float2(c2v, c3v);
                }
            }
        }
    }
}

// ------------------------------- driver --------------------------------------
extern "C" void kernel_launch(void* const* d_in, const int* in_sizes, int n_in,
                              void* d_out, int out_size)
{
    (void)in_sizes; (void)n_in; (void)out_size;
    const int*   ids   = (const int*)d_in[0];
    const int*   pos   = (const int*)d_in[1];
    const float* emb   = (const float*)d_in[2];
    const float* pemb  = (const float*)d_in[3];
    const float* normw = (const float*)d_in[4];
    const float* inw   = (const float*)d_in[5];
    const float* convw = (const float*)d_in[6];
    const float* convb = (const float*)d_in[7];
    const float* xpw   = (const float*)d_in[8];
    const float* dtw   = (const float*)d_in[9];
    const float* dtb   = (const float*)d_in[10];
    const float* Alog  = (const float*)d_in[11];
    const float* Dvec  = (const float*)d_in[12];
    const float* outw  = (const float*)d_in[13];
    const float* normf = (const float*)d_in[14];
    float* logits = (float*)d_out;

    static int attr_done = 0;
    if (!attr_done) {
        cudaFuncSetAttribute(gemm_mma, cudaFuncAttributeMaxDynamicSharedMemorySize, GEMM_SMEM);
        attr_done = 1;
    }

    float *hid, *res, *hs, *xz, *xc, *xd, *dtv, *Pv, *Sv, *hin;
    bf16 *ab, *wb;
    cudaGetSymbolAddress((void**)&hid, g_hidden);
    cudaGetSymbolAddress((void**)&res, g_residual);
    cudaGetSymbolAddress((void**)&hs,  g_hs);
    cudaGetSymbolAddress((void**)&xz,  g_xz);
    cudaGetSymbolAddress((void**)&xc,  g_xconv);
    cudaGetSymbolAddress((void**)&xd,  g_xdbl);
    cudaGetSymbolAddress((void**)&dtv, g_dt);
    cudaGetSymbolAddress((void**)&ab,  g_ab);
    cudaGetSymbolAddress((void**)&wb,  g_wb);
    cudaGetSymbolAddress((void**)&Pv,  g_P);
    cudaGetSymbolAddress((void**)&Sv,  g_S);
    cudaGetSymbolAddress((void**)&hin, g_hin);

    embed_kernel<<<(TOK*DM + 255)/256, 256>>>(ids, pos, emb, pemb, hid, res);

    for (int layer = 0; layer < NL; layer++) {
        addnorm_kernel<<<TOK, 256>>>(hid, res, normw + (size_t)layer*DM, hs, ab);

        // xz = hs @ in_proj^T : N=3072, K3=2304
        split3B_kernel<<<(2*DI*DM + 255)/256, 256>>>(inw + (size_t)layer*2*DI*DM, DM, DM, 2*DI*DM, wb);
        { dim3 g(TOK/128, 2*DI/128, 1);
          gemm_mma<<<g, 256, GEMM_SMEM>>>(ab, wb, xz, 2*DI, 3*DM, 2*DI, 0, 0, nullptr); }

        conv_silu_kernel<<<(TOK*DI + 255)/256, 256>>>(
            xz, convw + (size_t)layer*DI*4, convb + (size_t)layer*DI, xc, ab);

        // x_dbl = xc @ x_proj^T : N=80, K3=4608, split-K=8
        split3B_kernel<<<(XD*DI + 255)/256, 256>>>(xpw + (size_t)layer*XD*DI, DI, DI, XD*DI, wb);
        zero_kernel<<<(TOK*XD + 255)/256, 256>>>(xd, TOK*XD);
        { dim3 g(TOK/128, 1, 8);
          gemm_mma<<<g, 256, GEMM_SMEM>>>(ab, wb, xd, XD, 3*DI, XD, 1, 0, nullptr); }

        // dt = softplus(x_dbl[:, :48] @ dt_proj^T + dtb) : tensor core, K padded 160
        split3A_dt_kernel<<<(TOK*64 + 255)/256, 256>>>(xd, TOK*64, ab);
        split3B_dt_kernel<<<(DI*64 + 255)/256, 256>>>(dtw + (size_t)layer*DI*DTR, DI*64, wb);
        { dim3 g(TOK/128, DI/128, 1);
          gemm_mma<<<g, 256, GEMM_SMEM>>>(ab, wb, dtv, DI, DTKP, DI, 0, 1, dtb + (size_t)layer*DI); }

        // chunked selective scan
        scanA_kernel<<<(BB*DI*CH)/16, 256>>>(xc, dtv, xd, Alog + (size_t)layer*DI*DS, Pv, Sv);
        scanB_kernel<<<(BB*DI*DS + 255)/256, 256>>>(Pv, Sv, hin);
        scanC_kernel<<<(BB*DI*CH)/16, 256>>>(xc, dtv, xd, xz,
                                             Alog + (size_t)layer*DI*DS,
                                             Dvec + (size_t)layer*DI, hin, ab);

        // hid = y @ out_proj^T : N=768, K3=4608, split-K=3
        split3B_kernel<<<(DM*DI + 255)/256, 256>>>(outw + (size_t)layer*DM*DI, DI, DI, DM*DI, wb);
        zero_kernel<<<(TOK*DM + 255)/256, 256>>>(hid, TOK*DM);
        { dim3 g(TOK/128, DM/128, 3);
          gemm_mma<<<g, 256, GEMM_SMEM>>>(ab, wb, hid, DM, 3*DI, DM, 1, 0, nullptr); }
    }

    addnorm_kernel<<<TOK, 256>>>(hid, res, normf, hs, ab);

    // logits = hs[:, :384] @ emb^T : N=32000, K3=1152
    split3A_kernel<<<(TOK*DE + 255)/256, 256>>>(hs, DM, DE, TOK*DE, ab);
    split3B_kernel<<<(VOCAB_N*DE + 255)/256, 256>>>(emb, DE, DE, VOCAB_N*DE, wb);
    { dim3 g(TOK/128, (VOCAB_N + 127)/128, 1);
      gemm_mma<<<g, 256, GEMM_SMEM>>>(ab, wb, logits, VOCAB_N, 3*DE, VOCAB_N, 0, 0, nullptr); }
}

// round 7
// speedup vs baseline: 1.5177x; 1.5177x over previous
#include <cuda_runtime.h>
#include <cuda_fp16.h>
#include <cstdint>

#define BB 2
#define LL 1024
#define DM 768
#define DI 1536
#define DS 16
#define DTR 48
#define XD 80            // DT_RANK + 2*D_STATE
#define NL 6
#define VOCAB_N 32000
#define DE 384
#define TOK (BB*LL)      // 2048
#define CH 8             // scan chunks
#define CLEN 128         // steps per chunk
#define DTK 64           // padded K for dt projection (48 -> 64)

typedef __half fp16;

// ------------------------- scratch (no allocation allowed) -------------------
__device__ __align__(128) float g_hidden[TOK*DM];
__device__ __align__(128) float g_residual[TOK*DM];
__device__ __align__(128) float g_hs[TOK*DM];
__device__ __align__(128) float g_xz[TOK*2*DI];
__device__ __align__(128) float g_xconv[TOK*DI];
__device__ __align__(128) float g_xdbl[TOK*XD];
__device__ __align__(128) float g_dt[TOK*DI];
__device__ __align__(128) float g_P[BB*DI*CH*DS];
__device__ __align__(128) float g_S[BB*DI*CH*DS];
__device__ __align__(128) float g_hin[BB*DI*CH*DS];
__device__ __align__(128) fp16  g_hs16[TOK*DM];
__device__ __align__(128) fp16  g_xc16[TOK*DI];
__device__ __align__(128) fp16  g_y16[TOK*DI];
__device__ __align__(128) fp16  g_xd16[TOK*DTK];
__device__ __align__(128) fp16  g_hsde16[TOK*DE];
__device__ __align__(128) fp16  g_wb16[VOCAB_N*DE];   // weight cvt buffer (max = emb)

// ------------------------- embed ---------------------------------------------
__global__ void embed_kernel(const int* __restrict__ ids, const int* __restrict__ pos,
                             const float* __restrict__ emb, const float* __restrict__ pemb,
                             float* __restrict__ hidden, float* __restrict__ res)
{
    int idx = blockIdx.x * blockDim.x + threadIdx.x;
    if (idx >= TOK*DM) return;
    int t = idx / DM, c = idx % DM;
    float v;
    if (c < DE) v = emb[(size_t)ids[t]*DE + c];
    else        v = pemb[(size_t)pos[t]*DE + (c-DE)];
    hidden[idx] = v;
    res[idx] = 0.f;
}

__global__ void zero_kernel(float* __restrict__ p, int n)
{
    int i = blockIdx.x * blockDim.x + threadIdx.x;
    if (i < n) p[i] = 0.f;
}

// ----------- fp32 -> fp16 conversions ----------------------------------------
// generic: src rows stride lda, take K cols -> dst rows stride K (compact)
__global__ void cvt_kernel(const float* __restrict__ src, int lda, int K, int total,
                           fp16* __restrict__ dst)
{
    int idx = blockIdx.x * blockDim.x + threadIdx.x;
    if (idx >= total) return;
    int m = idx / K, k = idx - m*K;
    dst[(size_t)m*K + k] = __float2half(src[(size_t)m*lda + k]);
}
// padded: take Kin cols, write rows stride Kout, zero-fill Kin..Kout-1
__global__ void cvt_pad_kernel(const float* __restrict__ src, int lda, int Kin, int Kout,
                               int total, fp16* __restrict__ dst)
{
    int idx = blockIdx.x * blockDim.x + threadIdx.x;   // over M*Kout
    if (idx >= total) return;
    int m = idx / Kout, k = idx - m*Kout;
    float v = (k < Kin) ? src[(size_t)m*lda + k] : 0.f;
    dst[(size_t)m*Kout + k] = __float2half(v);
}

// ---- fused: res += hidden ; out = rmsnorm(res)*w ; + fp16 output ------------
__global__ __launch_bounds__(256) void addnorm_kernel(
    const float* __restrict__ h, float* __restrict__ res,
    const float* __restrict__ w, float* __restrict__ out, fp16* __restrict__ outs)
{
    int t = blockIdx.x;
    const float* hp = h + (size_t)t*DM;
    float* rp = res + (size_t)t*DM;
    float v[3];
    float ss = 0.f;
#pragma unroll
    for (int q = 0; q < 3; q++) {
        int i = threadIdx.x + q*256;
        v[q] = hp[i] + rp[i];
        ss += v[q]*v[q];
    }
#pragma unroll
    for (int o = 16; o > 0; o >>= 1) ss += __shfl_xor_sync(0xffffffffu, ss, o);
    __shared__ float red[8];
    if ((threadIdx.x & 31) == 0) red[threadIdx.x >> 5] = ss;
    __syncthreads();
    float tot = 0.f;
#pragma unroll
    for (int q = 0; q < 8; q++) tot += red[q];
    float rstd = rsqrtf(tot * (1.f/(float)DM) + 1e-5f);
#pragma unroll
    for (int q = 0; q < 3; q++) {
        int i = threadIdx.x + q*256;
        rp[i] = v[q];
        float u = v[q] * rstd * w[i];
        out[(size_t)t*DM + i] = u;
        outs[(size_t)t*DM + i] = __float2half(u);
    }
}

// ---- depthwise causal conv (width 4) + bias + silu (+fp16 output) ----------
__global__ void conv_silu_kernel(const float* __restrict__ xz,
                                 const float* __restrict__ cw,
                                 const float* __restrict__ cb,
                                 float* __restrict__ out, fp16* __restrict__ outs)
{
    int idx = blockIdx.x * blockDim.x + threadIdx.x;
    if (idx >= TOK*DI) return;
    int d = idx % DI;
    int t = idx / DI;
    int l = t % LL;
    float acc = cb[d];
    const float* base = xz + (size_t)t*(2*DI) + d;
#pragma unroll
    for (int j = 0; j < 4; j++) {
        int ll = l - 3 + j;
        if (ll >= 0) acc += cw[d*4+j] * base[(j-3)*(2*DI)];
    }
    float v = acc / (1.f + __expf(-acc));
    out[idx] = v;
    outs[idx] = __float2half(v);
}

// ---------------- chunked selective scan -------------------------------------
__global__ __launch_bounds__(256) void scanA_kernel(
    const float* __restrict__ xc, const float* __restrict__ dt,
    const float* __restrict__ xd, const float* __restrict__ A_log,
    float* __restrict__ Pv, float* __restrict__ Sv)
{
    int tid = threadIdx.x;
    int u = blockIdx.x * 16 + (tid >> 4);   // (pair, chunk)
    int n = tid & 15;
    int p = u >> 3;                          // CH=8
    int c = u & 7;
    int b = p / DI, d = p - b*DI;
    float A = -__expf(A_log[d*DS + n]);
    const float* xcb = xc + (size_t)b*LL*DI + d;
    const float* dtb = dt + (size_t)b*LL*DI + d;
    const float* xdb = xd + (size_t)b*LL*XD + DTR + n;
    int l0 = c * CLEN;
    float P = 1.f, h = 0.f;
#pragma unroll 4
    for (int i = 0; i < CLEN; i++) {
        int l = l0 + i;
        float xv  = xcb[(size_t)l*DI];
        float dtv = dtb[(size_t)l*DI];
        float Bv  = xdb[(size_t)l*XD];
        float dA  = __expf(dtv * A);
        P *= dA;
        h = dA*h + (dtv*xv)*Bv;
    }
    Pv[(size_t)u*DS + n] = P;
    Sv[(size_t)u*DS + n] = h;
}

__global__ void scanB_kernel(const float* __restrict__ Pv, const float* __restrict__ Sv,
                             float* __restrict__ hin)
{
    int g = blockIdx.x * blockDim.x + threadIdx.x;
    if (g >= BB*DI*DS) return;
    int p = g / DS, n = g - p*DS;
    float h = 0.f;
#pragma unroll
    for (int c = 0; c < CH; c++) {
        size_t idx = ((size_t)p*CH + c)*DS + n;
        hin[idx] = h;
        h = Pv[idx]*h + Sv[idx];
    }
}

__global__ __launch_bounds__(256) void scanC_kernel(
    const float* __restrict__ xc, const float* __restrict__ dt,
    const float* __restrict__ xd, const float* __restrict__ xz,
    const float* __restrict__ A_log, const float* __restrict__ Dv,
    const float* __restrict__ hin, fp16* __restrict__ ys)
{
    int tid = threadIdx.x;
    int u = blockIdx.x * 16 + (tid >> 4);
    int n = tid & 15;
    int p = u >> 3;
    int c = u & 7;
    int b = p / DI, d = p - b*DI;
    float A = -__expf(A_log[d*DS + n]);
    float Dval = Dv[d];
    const float* xcb = xc + (size_t)b*LL*DI + d;
    const float* dtb = dt + (size_t)b*LL*DI + d;
    const float* xdb = xd + (size_t)b*LL*XD + DTR + n;
    const float* xzb = xz + (size_t)b*LL*(2*DI) + DI + d;
    fp16* yb = ys + (size_t)b*LL*DI + d;
    int l0 = c * CLEN;
    float h = hin[(size_t)u*DS + n];
#pragma unroll 4
    for (int i = 0; i < CLEN; i++) {
        int l = l0 + i;
        float xv  = xcb[(size_t)l*DI];
        float dtv = dtb[(size_t)l*DI];
        float Bv  = xdb[(size_t)l*XD];
        float Cv  = xdb[(size_t)l*XD + DS];
        float dA  = __expf(dtv * A);
        h = dA*h + (dtv*xv)*Bv;
        float part = h*Cv;
        part += __shfl_xor_sync(0xffffffffu, part, 1);
        part += __shfl_xor_sync(0xffffffffu, part, 2);
        part += __shfl_xor_sync(0xffffffffu, part, 4);
        part += __shfl_xor_sync(0xffffffffu, part, 8);
        if (n == 0) {
            float z = xzb[(size_t)l*(2*DI)];
            float sig = 1.f / (1.f + __expf(-z));
            float v = (part + xv*Dval) * (z * sig);
            yb[(size_t)l*DI] = __float2half(v);
        }
    }
}

// --------------------------- tensor-core GEMM (fp16) -------------------------
// C[m,n] = sum_k A[m,k]*B[n,k]. 128x128 block, BK=32, 4-stage cp.async pipeline.
__device__ __forceinline__ void ldsm_x4(uint32_t* r, uint32_t addr){
    asm volatile("ldmatrix.sync.aligned.m8n8.x4.shared.b16 {%0,%1,%2,%3}, [%4];"
      : "=r"(r[0]),"=r"(r[1]),"=r"(r[2]),"=r"(r[3]) : "r"(addr));
}
__device__ __forceinline__ void mma_fp16(float* c, const uint32_t* a, const uint32_t* b){
    asm volatile("mma.sync.aligned.m16n8k16.row.col.f32.f16.f16.f32 "
      "{%0,%1,%2,%3}, {%4,%5,%6,%7}, {%8,%9}, {%0,%1,%2,%3};"
      : "+f"(c[0]),"+f"(c[1]),"+f"(c[2]),"+f"(c[3])
      : "r"(a[0]),"r"(a[1]),"r"(a[2]),"r"(a[3]), "r"(b[0]),"r"(b[1]));
}
__device__ __forceinline__ void cp16(uint32_t daddr, const void* gptr, uint32_t srcsz){
    asm volatile("cp.async.cg.shared.global [%0], [%1], 16, %2;\n"
      :: "r"(daddr), "l"(gptr), "r"(srcsz));
}

#define SSTRIDE 40
#define STAGE_ELEM (128*SSTRIDE)
#define STAGE_BYTES (STAGE_ELEM*2)
#define NSTAGE 4
#define GEMM_SMEM (NSTAGE*2*STAGE_BYTES)   // 81920 B

__global__ __launch_bounds__(256,2) void gemm_mma(
    const fp16* __restrict__ A, const fp16* __restrict__ B,
    float* __restrict__ C, int N, int K2, int ldc,
    int katomic, int epi, const float* __restrict__ bias)
{
    extern __shared__ __align__(16) fp16 smem[];
    const int tid = threadIdx.x;
    const int lane = tid & 31, wid = tid >> 5;
    const int wm = wid & 1, wn = wid >> 1;
    const int bm = blockIdx.x * 128, bn = blockIdx.y * 128;

    const int ksplit = gridDim.z;
    const int per = (K2 / 32) / ksplit;
    const int kbeg = blockIdx.z * per * 32;
    const int iters = per;

    const int r0 = tid >> 2,            c0 = (tid & 3) * 8;
    const int r1 = (tid + 256) >> 2,    c1 = ((tid + 256) & 3) * 8;

    uint32_t sbase = (uint32_t)__cvta_generic_to_shared(smem);

    const int bw0 = bn + r0, bw1 = bn + r1;
    const bool bv0 = bw0 < N, bv1 = bw1 < N;
    const fp16* Bq0 = B + (size_t)(bv0 ? bw0 : 0)*K2;
    const fp16* Bq1 = B + (size_t)(bv1 ? bw1 : 0)*K2;
    const fp16* Aq0 = A + (size_t)(bm + r0)*K2;
    const fp16* Aq1 = A + (size_t)(bm + r1)*K2;

    const uint32_t aoff0 = (uint32_t)(r0*SSTRIDE + c0)*2;
    const uint32_t aoff1 = (uint32_t)(r1*SSTRIDE + c1)*2;

    float acc[4][4][4];
#pragma unroll
    for (int i = 0; i < 4; i++)
#pragma unroll
        for (int j = 0; j < 4; j++)
#pragma unroll
            for (int q = 0; q < 4; q++) acc[i][j][q] = 0.f;

    // prologue: stages 0..NSTAGE-2
#pragma unroll
    for (int s = 0; s < NSTAGE-1; s++) {
        if (s < iters) {
            int k = kbeg + s*32;
            uint32_t sA = sbase + (uint32_t)s*STAGE_BYTES;
            uint32_t sB = sbase + (uint32_t)(NSTAGE + s)*STAGE_BYTES;
            cp16(sA + aoff0, Aq0 + k + c0, 16u);
            cp16(sA + aoff1, Aq1 + k + c1, 16u);
            cp16(sB + aoff0, Bq0 + k + c0, bv0 ? 16u : 0u);
            cp16(sB + aoff1, Bq1 + k + c1, bv1 ? 16u : 0u);
        }
        asm volatile("cp.async.commit_group;\n" ::: "memory");
    }

    const int ar  = lane & 15;
    const int ak  = (lane >> 4) * 8;
    const int brr = (lane & 7) + ((lane >> 4) & 1)*8;
    const int bk  = ((lane >> 3) & 1) * 8;

    for (int it = 0; it < iters; it++) {
        int rem = iters - 1 - it;
        if (rem >= 2)      { asm volatile("cp.async.wait_group 2;\n" ::: "memory"); }
        else if (rem == 1) { asm volatile("cp.async.wait_group 1;\n" ::: "memory"); }
        else               { asm volatile("cp.async.wait_group 0;\n" ::: "memory"); }
        __syncthreads();

        {
            int s = it + NSTAGE - 1;
            if (s < iters) {
                int k = kbeg + s*32;
                int bufn = s & (NSTAGE-1);
                uint32_t sA = sbase + (uint32_t)bufn*STAGE_BYTES;
                uint32_t sB = sbase + (uint32_t)(NSTAGE + bufn)*STAGE_BYTES;
                cp16(sA + aoff0, Aq0 + k + c0, 16u);
                cp16(sA + aoff1, Aq1 + k + c1, 16u);
                cp16(sB + aoff0, Bq0 + k + c0, bv0 ? 16u : 0u);
                cp16(sB + aoff1, Bq1 + k + c1, bv1 ? 16u : 0u);
                asm volatile("cp.async.commit_group;\n" ::: "memory");
            }
        }

        int buf = it & (NSTAGE-1);
        uint32_t sAc = sbase + (uint32_t)buf*STAGE_BYTES;
        uint32_t sBc = sbase + (uint32_t)(NSTAGE + buf)*STAGE_BYTES;
#pragma unroll
        for (int kk = 0; kk < 2; kk++) {
            uint32_t afr[4][4], bfr[4][2];
#pragma unroll
            for (int mi = 0; mi < 4; mi++) {
                int row = wm*64 + mi*16 + ar;
                ldsm_x4(afr[mi], sAc + (uint32_t)(row*SSTRIDE + kk*16 + ak)*2);
            }
#pragma unroll
            for (int np = 0; np < 2; np++) {
                int row = wn*32 + np*16 + brr;
                uint32_t q4[4];
                ldsm_x4(q4, sBc + (uint32_t)(row*SSTRIDE + kk*16 + bk)*2);
                bfr[np*2+0][0]=q4[0]; bfr[np*2+0][1]=q4[1];
                bfr[np*2+1][0]=q4[2]; bfr[np*2+1][1]=q4[3];
            }
#pragma unroll
            for (int mi = 0; mi < 4; mi++)
#pragma unroll
                for (int ni = 0; ni < 4; ni++)
                    mma_fp16(acc[mi][ni], afr[mi], bfr[ni]);
        }
    }

    const int grp = lane >> 2, qd = lane & 3;
#pragma unroll
    for (int mi = 0; mi < 4; mi++) {
        int m = bm + wm*64 + mi*16 + grp;
#pragma unroll
        for (int ni = 0; ni < 4; ni++) {
            int n = bn + wn*32 + ni*8 + qd*2;
            if (n < N) {
                float c0v = acc[mi][ni][0], c1v = acc[mi][ni][1];
                float c2v = acc[mi][ni][2], c3v = acc[mi][ni][3];
                if (epi == 1) {
                    float b0 = bias[n], b1 = bias[n+1];
                    float x0 = c0v + b0, x1 = c1v + b1, x2 = c2v + b0, x3 = c3v + b1;
                    c0v = (x0 > 20.f) ? x0 : log1pf(__expf(x0));
                    c1v = (x1 > 20.f) ? x1 : log1pf(__expf(x1));
                    c2v = (x2 > 20.f) ? x2 : log1pf(__expf(x2));
                    c3v = (x3 > 20.f) ? x3 : log1pf(__expf(x3));
                }
                if (katomic) {
                    atomicAdd(&C[(size_t)m*ldc + n],       c0v);
                    if (n+1 < N) atomicAdd(&C[(size_t)m*ldc + n+1], c1v);
                    atomicAdd(&C[(size_t)(m+8)*ldc + n],   c2v);
                    if (n+1 < N) atomicAdd(&C[(size_t)(m+8)*ldc + n+1], c3v);
                } else {
                    *(float2*)(&C[(size_t)m*ldc + n])     = make_float2(c0v, c1v);
                    *(float2*)(&C[(size_t)(m+8)*ldc + n]) = make_float2(c2v, c3v);
                }
            }
        }
    }
}

// ------------------------------- driver --------------------------------------
extern "C" void kernel_launch(void* const* d_in, const int* in_sizes, int n_in,
                              void* d_out, int out_size)
{
    (void)in_sizes; (void)n_in; (void)out_size;
    const int*   ids   = (const int*)d_in[0];
    const int*   pos   = (const int*)d_in[1];
    const float* emb   = (const float*)d_in[2];
    const float* pemb  = (const float*)d_in[3];
    const float* normw = (const float*)d_in[4];
    const float* inw   = (const float*)d_in[5];
    const float* convw = (const float*)d_in[6];
    const float* convb = (const float*)d_in[7];
    const float* xpw   = (const float*)d_in[8];
    const float* dtw   = (const float*)d_in[9];
    const float* dtb   = (const float*)d_in[10];
    const float* Alog  = (const float*)d_in[11];
    const float* Dvec  = (const float*)d_in[12];
    const float* outw  = (const float*)d_in[13];
    const float* normf = (const float*)d_in[14];
    float* logits = (float*)d_out;

    static int attr_done = 0;
    if (!attr_done) {
        cudaFuncSetAttribute(gemm_mma, cudaFuncAttributeMaxDynamicSharedMemorySize, GEMM_SMEM);
        attr_done = 1;
    }

    float *hid, *res, *hs, *xz, *xc, *xd, *dtv, *Pv, *Sv, *hin;
    fp16 *hs16, *xc16, *y16, *xd16, *hsde16, *wb;
    cudaGetSymbolAddress((void**)&hid, g_hidden);
    cudaGetSymbolAddress((void**)&res, g_residual);
    cudaGetSymbolAddress((void**)&hs,  g_hs);
    cudaGetSymbolAddress((void**)&xz,  g_xz);
    cudaGetSymbolAddress((void**)&xc,  g_xconv);
    cudaGetSymbolAddress((void**)&xd,  g_xdbl);
    cudaGetSymbolAddress((void**)&dtv, g_dt);
    cudaGetSymbolAddress((void**)&Pv,  g_P);
    cudaGetSymbolAddress((void**)&Sv,  g_S);
    cudaGetSymbolAddress((void**)&hin, g_hin);
    cudaGetSymbolAddress((void**)&hs16,   g_hs16);
    cudaGetSymbolAddress((void**)&xc16,   g_xc16);
    cudaGetSymbolAddress((void**)&y16,    g_y16);
    cudaGetSymbolAddress((void**)&xd16,   g_xd16);
    cudaGetSymbolAddress((void**)&hsde16, g_hsde16);
    cudaGetSymbolAddress((void**)&wb,     g_wb16);

    embed_kernel<<<(TOK*DM + 255)/256, 256>>>(ids, pos, emb, pemb, hid, res);

    for (int layer = 0; layer < NL; layer++) {
        addnorm_kernel<<<TOK, 256>>>(hid, res, normw + (size_t)layer*DM, hs, hs16);

        // xz = hs @ in_proj^T : N=3072, K=768
        cvt_kernel<<<(2*DI*DM + 255)/256, 256>>>(inw + (size_t)layer*2*DI*DM, DM, DM, 2*DI*DM, wb);
        { dim3 g(TOK/128, 2*DI/128, 1);
          gemm_mma<<<g, 256, GEMM_SMEM>>>(hs16, wb, xz, 2*DI, DM, 2*DI, 0, 0, nullptr); }

        conv_silu_kernel<<<(TOK*DI + 255)/256, 256>>>(
            xz, convw + (size_t)layer*DI*4, convb + (size_t)layer*DI, xc, xc16);

        // x_dbl = xc @ x_proj^T : N=80, K=1536, split-K=8
        cvt_kernel<<<(XD*DI + 255)/256, 256>>>(xpw + (size_t)layer*XD*DI, DI, DI, XD*DI, wb);
        zero_kernel<<<(TOK*XD + 255)/256, 256>>>(xd, TOK*XD);
        { dim3 g(TOK/128, 1, 8);
          gemm_mma<<<g, 256, GEMM_SMEM>>>(xc16, wb, xd, XD, DI, XD, 1, 0, nullptr); }

        // dt = softplus(x_dbl[:, :48] @ dt_proj^T + dtb) : K padded 48->64
        cvt_pad_kernel<<<(TOK*DTK + 255)/256, 256>>>(xd, XD, DTR, DTK, TOK*DTK, xd16);
        cvt_pad_kernel<<<(DI*DTK + 255)/256, 256>>>(dtw + (size_t)layer*DI*DTR, DTR, DTR, DTK, DI*DTK, wb);
        { dim3 g(TOK/128, DI/128, 1);
          gemm_mma<<<g, 256, GEMM_SMEM>>>(xd16, wb, dtv, DI, DTK, DI, 0, 1, dtb + (size_t)layer*DI); }

        // chunked selective scan
        scanA_kernel<<<(BB*DI*CH)/16, 256>>>(xc, dtv, xd, Alog + (size_t)layer*DI*DS, Pv, Sv);
        scanB_kernel<<<(BB*DI*DS + 255)/256, 256>>>(Pv, Sv, hin);
        scanC_kernel<<<(BB*DI*CH)/16, 256>>>(xc, dtv, xd, xz,
                                             Alog + (size_t)layer*DI*DS,
                                             Dvec + (size_t)layer*DI, hin, y16);

        // hid = y @ out_proj^T : N=768, K=1536, split-K=3
        cvt_kernel<<<(DM*DI + 255)/256, 256>>>(outw + (size_t)layer*DM*DI, DI, DI, DM*DI, wb);
        zero_kernel<<<(TOK*DM + 255)/256, 256>>>(hid, TOK*DM);
        { dim3 g(TOK/128, DM/128, 3);
          gemm_mma<<<g, 256, GEMM_SMEM>>>(y16, wb, hid, DM, DI, DM, 1, 0, nullptr); }
    }

    addnorm_kernel<<<TOK, 256>>>(hid, res, normf, hs, hs16);

    // logits = hs[:, :384] @ emb^T : N=32000, K=384
    cvt_kernel<<<(TOK*DE + 255)/256, 256>>>(hs, DM, DE, TOK*DE, hsde16);
    cvt_kernel<<<(VOCAB_N*DE + 255)/256, 256>>>(emb, DE, DE, VOCAB_N*DE, wb);
    { dim3 g(TOK/128, (VOCAB_N + 127)/128, 1);
      gemm_mma<<<g, 256, GEMM_SMEM>>>(hsde16, wb, logits, VOCAB_N, DE, VOCAB_N, 0, 0, nullptr); }
}

// round 9
// speedup vs baseline: 2.3267x; 1.5330x over previous
#include <cuda_runtime.h>
#include <cuda_fp16.h>
#include <cstdint>

#define BB 2
#define LL 1024
#define DM 768
#define DI 1536
#define DS 16
#define DTR 48
#define XD 80            // DT_RANK + 2*D_STATE
#define NL 6
#define VOCAB_N 32000
#define DE 384
#define TOK (BB*LL)      // 2048
#define CH 32            // scan chunks
#define CLEN 32          // steps per chunk (LL/CH)
#define DTK 64           // padded K for dt projection (48 -> 64)

typedef __half fp16;

// ------------------------- scratch (no allocation allowed) -------------------
__device__ __align__(128) float g_hidden[TOK*DM];
__device__ __align__(128) float g_residual[TOK*DM];
__device__ __align__(128) float g_hs[TOK*DM];
__device__ __align__(128) float g_xz[TOK*2*DI];
__device__ __align__(128) float g_xconv[TOK*DI];
__device__ __align__(128) float g_xdbl[TOK*XD];
__device__ __align__(128) float g_dt[TOK*DI];
__device__ __align__(128) float g_P[BB*DI*CH*DS];
__device__ __align__(128) float g_S[BB*DI*CH*DS];
__device__ __align__(128) float g_hin[BB*DI*CH*DS];
__device__ __align__(128) fp16  g_hs16[TOK*DM];
__device__ __align__(128) fp16  g_xc16[TOK*DI];
__device__ __align__(128) fp16  g_y16[TOK*DI];
__device__ __align__(128) fp16  g_xd16[TOK*DTK];
__device__ __align__(128) fp16  g_hsde16[TOK*DE];
__device__ __align__(128) fp16  g_wb16[VOCAB_N*DE];   // weight cvt buffer (max = emb)

// ------------------------- embed ---------------------------------------------
__global__ void embed_kernel(const int* __restrict__ ids, const int* __restrict__ pos,
                             const float* __restrict__ emb, const float* __restrict__ pemb,
                             float* __restrict__ hidden, float* __restrict__ res)
{
    int idx = blockIdx.x * blockDim.x + threadIdx.x;
    if (idx >= TOK*DM) return;
    int t = idx / DM, c = idx % DM;
    float v;
    if (c < DE) v = emb[(size_t)ids[t]*DE + c];
    else        v = pemb[(size_t)pos[t]*DE + (c-DE)];
    hidden[idx] = v;
    res[idx] = 0.f;
}

__global__ void zero_kernel(float* __restrict__ p, int n)
{
    int i = blockIdx.x * blockDim.x + threadIdx.x;
    if (i < n) p[i] = 0.f;
}

// ----------- fp32 -> fp16 conversions ----------------------------------------
__global__ void cvt_kernel(const float* __restrict__ src, int lda, int K, int total,
                           fp16* __restrict__ dst)
{
    int idx = blockIdx.x * blockDim.x + threadIdx.x;
    if (idx >= total) return;
    int m = idx / K, k = idx - m*K;
    dst[(size_t)m*K + k] = __float2half(src[(size_t)m*lda + k]);
}
__global__ void cvt_pad_kernel(const float* __restrict__ src, int lda, int Kin, int Kout,
                               int total, fp16* __restrict__ dst)
{
    int idx = blockIdx.x * blockDim.x + threadIdx.x;
    if (idx >= total) return;
    int m = idx / Kout, k = idx - m*Kout;
    float v = (k < Kin) ? src[(size_t)m*lda + k] : 0.f;
    dst[(size_t)m*Kout + k] = __float2half(v);
}

// ---- fused: res += hidden ; out = rmsnorm(res)*w ; + fp16 output ------------
__global__ __launch_bounds__(256) void addnorm_kernel(
    const float* __restrict__ h, float* __restrict__ res,
    const float* __restrict__ w, float* __restrict__ out, fp16* __restrict__ outs)
{
    int t = blockIdx.x;
    const float* hp = h + (size_t)t*DM;
    float* rp = res + (size_t)t*DM;
    float v[3];
    float ss = 0.f;
#pragma unroll
    for (int q = 0; q < 3; q++) {
        int i = threadIdx.x + q*256;
        v[q] = hp[i] + rp[i];
        ss += v[q]*v[q];
    }
#pragma unroll
    for (int o = 16; o > 0; o >>= 1) ss += __shfl_xor_sync(0xffffffffu, ss, o);
    __shared__ float red[8];
    if ((threadIdx.x & 31) == 0) red[threadIdx.x >> 5] = ss;
    __syncthreads();
    float tot = 0.f;
#pragma unroll
    for (int q = 0; q < 8; q++) tot += red[q];
    float rstd = rsqrtf(tot * (1.f/(float)DM) + 1e-5f);
#pragma unroll
    for (int q = 0; q < 3; q++) {
        int i = threadIdx.x + q*256;
        rp[i] = v[q];
        float u = v[q] * rstd * w[i];
        out[(size_t)t*DM + i] = u;
        outs[(size_t)t*DM + i] = __float2half(u);
    }
}

// ---- depthwise causal conv (width 4) + bias + silu (+fp16 output) ----------
__global__ void conv_silu_kernel(const float* __restrict__ xz,
                                 const float* __restrict__ cw,
                                 const float* __restrict__ cb,
                                 float* __restrict__ out, fp16* __restrict__ outs)
{
    int idx = blockIdx.x * blockDim.x + threadIdx.x;
    if (idx >= TOK*DI) return;
    int d = idx % DI;
    int t = idx / DI;
    int l = t % LL;
    float acc = cb[d];
    const float* base = xz + (size_t)t*(2*DI) + d;
#pragma unroll
    for (int j = 0; j < 4; j++) {
        int ll = l - 3 + j;
        if (ll >= 0) acc += cw[d*4+j] * base[(j-3)*(2*DI)];
    }
    float v = acc / (1.f + __expf(-acc));
    out[idx] = v;
    outs[idx] = __float2half(v);
}

// ---------------- chunked selective scan (register-state) --------------------
// thread <-> (b, c, d), d fastest. 16 states in registers.
// pw[n] = r^(n+1) built by a shallow multiply tree.
__device__ __forceinline__ void build_powers(float r, float* pw)
{
    pw[0] = r;
#pragma unroll
    for (int n = 1; n < DS; n++) {
        int m = n + 1;  // want r^m
        pw[n] = pw[m/2 - 1] * pw[(m - m/2) - 1];
    }
}

// pass A: per (b,c,d): P[n] = prod dA[n], S[n] = state from h_in=0
__global__ __launch_bounds__(256) void scanA_kernel(
    const float* __restrict__ xc, const float* __restrict__ dt,
    const float* __restrict__ xd, const float* __restrict__ A_log,
    float* __restrict__ Pv, float* __restrict__ Sv)
{
    int g = blockIdx.x * 256 + threadIdx.x;     // ((b*CH + c)*DI + d)
    int d = g % DI;
    int bc = g / DI;
    int c = bc % CH;
    int b = bc / CH;
    float A[DS];
    bool fast = true;
#pragma unroll
    for (int n = 0; n < DS; n++) A[n] = -__expf(A_log[d*DS + n]);
    float A1 = A[0];
#pragma unroll
    for (int n = 0; n < DS; n++)
        fast = fast && (fabsf(A[n] - (float)(n+1)*A1) <= 1e-4f*fabsf(A[n]));

    int l0 = c * CLEN;
    const float* xcb = xc + ((size_t)b*LL + l0)*DI + d;
    const float* dtb = dt + ((size_t)b*LL + l0)*DI + d;
    const float* xdb = xd + ((size_t)b*LL + l0)*XD + DTR;   // B at +0 (n fastest)

    float h[DS];
#pragma unroll
    for (int n = 0; n < DS; n++) h[n] = 0.f;

    if (fast) {
        float rp = 1.f;
        for (int i = 0; i < CLEN; i++) {
            float xv  = xcb[(size_t)i*DI];
            float dtv = dtb[(size_t)i*DI];
            float Bv[DS];
#pragma unroll
            for (int q = 0; q < 4; q++)
                *(float4*)(Bv + q*4) = *(const float4*)(xdb + (size_t)i*XD + q*4);
            float w = dtv * xv;
            float r = __expf(dtv * A1);
            rp *= r;
            float pw[DS];
            build_powers(r, pw);
#pragma unroll
            for (int n = 0; n < DS; n++) h[n] = pw[n]*h[n] + w*Bv[n];
        }
        float pp[DS];
        build_powers(rp, pp);
#pragma unroll
        for (int q = 0; q < 4; q++) {
            *(float4*)&Pv[(size_t)g*DS + q*4] = *(float4*)(pp + q*4);
            *(float4*)&Sv[(size_t)g*DS + q*4] = *(float4*)(h + q*4);
        }
    } else {
        float P[DS];
#pragma unroll
        for (int n = 0; n < DS; n++) P[n] = 1.f;
        for (int i = 0; i < CLEN; i++) {
            float xv  = xcb[(size_t)i*DI];
            float dtv = dtb[(size_t)i*DI];
            float Bv[DS];
#pragma unroll
            for (int q = 0; q < 4; q++)
                *(float4*)(Bv + q*4) = *(const float4*)(xdb + (size_t)i*XD + q*4);
            float w = dtv * xv;
#pragma unroll
            for (int n = 0; n < DS; n++) {
                float dA = __expf(dtv * A[n]);
                P[n] *= dA;
                h[n] = dA*h[n] + w*Bv[n];
            }
        }
#pragma unroll
        for (int q = 0; q < 4; q++) {
            *(float4*)&Pv[(size_t)g*DS + q*4] = *(float4*)(P + q*4);
            *(float4*)&Sv[(size_t)g*DS + q*4] = *(float4*)(h + q*4);
        }
    }
}

// pass B: serial combine over chunks -> h_in per chunk
__global__ void scanB_kernel(const float* __restrict__ Pv, const float* __restrict__ Sv,
                             float* __restrict__ hin)
{
    int g = blockIdx.x * blockDim.x + threadIdx.x;   // (b*DI + d)*DS + n
    if (g >= BB*DI*DS) return;
    int n = g % DS;
    int pd = g / DS;
    int d = pd % DI;
    int b = pd / DI;
    float h = 0.f;
#pragma unroll
    for (int c = 0; c < CH; c++) {
        size_t idx = ((size_t)(b*CH + c)*DI + d)*DS + n;
        hin[idx] = h;
        h = Pv[idx]*h + Sv[idx];
    }
}

// pass C: rescan chunk from h_in, produce y*silu(z) in fp16
__global__ __launch_bounds__(256) void scanC_kernel(
    const float* __restrict__ xc, const float* __restrict__ dt,
    const float* __restrict__ xd, const float* __restrict__ xz,
    const float* __restrict__ A_log, const float* __restrict__ Dv,
    const float* __restrict__ hin, fp16* __restrict__ ys)
{
    int g = blockIdx.x * 256 + threadIdx.x;
    int d = g % DI;
    int bc = g / DI;
    int c = bc % CH;
    int b = bc / CH;
    float A[DS];
    bool fast = true;
#pragma unroll
    for (int n = 0; n < DS; n++) A[n] = -__expf(A_log[d*DS + n]);
    float A1 = A[0];
#pragma unroll
    for (int n = 0; n < DS; n++)
        fast = fast && (fabsf(A[n] - (float)(n+1)*A1) <= 1e-4f*fabsf(A[n]));
    float Dval = Dv[d];

    int l0 = c * CLEN;
    const float* xcb = xc + ((size_t)b*LL + l0)*DI + d;
    const float* dtb = dt + ((size_t)b*LL + l0)*DI + d;
    const float* xdb = xd + ((size_t)b*LL + l0)*XD + DTR;
    const float* xzb = xz + ((size_t)b*LL + l0)*(2*DI) + DI + d;
    fp16* yb = ys + ((size_t)b*LL + l0)*DI + d;

    float h[DS];
#pragma unroll
    for (int q = 0; q < 4; q++)
        *(float4*)(h + q*4) = *(const float4*)&hin[(size_t)g*DS + q*4];

    for (int i = 0; i < CLEN; i++) {
        float xv  = xcb[(size_t)i*DI];
        float dtv = dtb[(size_t)i*DI];
        float Bv[DS], Cv[DS];
#pragma unroll
        for (int q = 0; q < 4; q++) {
            *(float4*)(Bv + q*4) = *(const float4*)(xdb + (size_t)i*XD + q*4);
            *(float4*)(Cv + q*4) = *(const float4*)(xdb + (size_t)i*XD + DS + q*4);
        }
        float w = dtv * xv;
        float y = 0.f;
        if (fast) {
            float r = __expf(dtv * A1);
            float pw[DS];
            build_powers(r, pw);
#pragma unroll
            for (int n = 0; n < DS; n++) {
                h[n] = pw[n]*h[n] + w*Bv[n];
                y += h[n]*Cv[n];
            }
        } else {
#pragma unroll
            for (int n = 0; n < DS; n++) {
                float dA = __expf(dtv * A[n]);
                h[n] = dA*h[n] + w*Bv[n];
                y += h[n]*Cv[n];
            }
        }
        float z = xzb[(size_t)i*(2*DI)];
        float sig = 1.f / (1.f + __expf(-z));
        float v = (y + xv*Dval) * (z * sig);
        yb[(size_t)i*DI] = __float2half(v);
    }
}

// --------------------------- tensor-core GEMM (fp16) -------------------------
// C[m,n] = sum_k A[m,k]*B[n,k]. 128x128 block, BK=32, 4-stage cp.async pipeline.
__device__ __forceinline__ void ldsm_x4(uint32_t* r, uint32_t addr){
    asm volatile("ldmatrix.sync.aligned.m8n8.x4.shared.b16 {%0,%1,%2,%3}, [%4];"
      : "=r"(r[0]),"=r"(r[1]),"=r"(r[2]),"=r"(r[3]) : "r"(addr));
}
__device__ __forceinline__ void mma_fp16(float* c, const uint32_t* a, const uint32_t* b){
    asm volatile("mma.sync.aligned.m16n8k16.row.col.f32.f16.f16.f32 "
      "{%0,%1,%2,%3}, {%4,%5,%6,%7}, {%8,%9}, {%0,%1,%2,%3};"
      : "+f"(c[0]),"+f"(c[1]),"+f"(c[2]),"+f"(c[3])
      : "r"(a[0]),"r"(a[1]),"r"(a[2]),"r"(a[3]), "r"(b[0]),"r"(b[1]));
}
__device__ __forceinline__ void cp16(uint32_t daddr, const void* gptr, uint32_t srcsz){
    asm volatile("cp.async.cg.shared.global [%0], [%1], 16, %2;\n"
      :: "r"(daddr), "l"(gptr), "r"(srcsz));
}

#define SSTRIDE 40
#define STAGE_ELEM (128*SSTRIDE)
#define STAGE_BYTES (STAGE_ELEM*2)
#define NSTAGE 4
#define GEMM_SMEM (NSTAGE*2*STAGE_BYTES)   // 81920 B

__global__ __launch_bounds__(256,2) void gemm_mma(
    const fp16* __restrict__ A, const fp16* __restrict__ B,
    float* __restrict__ C, int N, int K2, int ldc,
    int katomic, int epi, const float* __restrict__ bias)
{
    extern __shared__ __align__(16) fp16 smem[];
    const int tid = threadIdx.x;
    const int lane = tid & 31, wid = tid >> 5;
    const int wm = wid & 1, wn = wid >> 1;
    const int bm = blockIdx.x * 128, bn = blockIdx.y * 128;

    const int ksplit = gridDim.z;
    const int per = (K2 / 32) / ksplit;
    const int kbeg = blockIdx.z * per * 32;
    const int iters = per;

    const int r0 = tid >> 2,            c0 = (tid & 3) * 8;
    const int r1 = (tid + 256) >> 2,    c1 = ((tid + 256) & 3) * 8;

    uint32_t sbase = (uint32_t)__cvta_generic_to_shared(smem);

    const int bw0 = bn + r0, bw1 = bn + r1;
    const bool bv0 = bw0 < N, bv1 = bw1 < N;
    const fp16* Bq0 = B + (size_t)(bv0 ? bw0 : 0)*K2;
    const fp16* Bq1 = B + (size_t)(bv1 ? bw1 : 0)*K2;
    const fp16* Aq0 = A + (size_t)(bm + r0)*K2;
    const fp16* Aq1 = A + (size_t)(bm + r1)*K2;

    const uint32_t aoff0 = (uint32_t)(r0*SSTRIDE + c0)*2;
    const uint32_t aoff1 = (uint32_t)(r1*SSTRIDE + c1)*2;

    float acc[4][4][4];
#pragma unroll
    for (int i = 0; i < 4; i++)
#pragma unroll
        for (int j = 0; j < 4; j++)
#pragma unroll
            for (int q = 0; q < 4; q++) acc[i][j][q] = 0.f;

#pragma unroll
    for (int s = 0; s < NSTAGE-1; s++) {
        if (s < iters) {
            int k = kbeg + s*32;
            uint32_t sA = sbase + (uint32_t)s*STAGE_BYTES;
            uint32_t sB = sbase + (uint32_t)(NSTAGE + s)*STAGE_BYTES;
            cp16(sA + aoff0, Aq0 + k + c0, 16u);
            cp16(sA + aoff1, Aq1 + k + c1, 16u);
            cp16(sB + aoff0, Bq0 + k + c0, bv0 ? 16u : 0u);
            cp16(sB + aoff1, Bq1 + k + c1, bv1 ? 16u : 0u);
        }
        asm volatile("cp.async.commit_group;\n" ::: "memory");
    }

    const int ar  = lane & 15;
    const int ak  = (lane >> 4) * 8;
    const int brr = (lane & 7) + ((lane >> 4) & 1)*8;
    const int bk  = ((lane >> 3) & 1) * 8;

    for (int it = 0; it < iters; it++) {
        int rem = iters - 1 - it;
        if (rem >= 2)      { asm volatile("cp.async.wait_group 2;\n" ::: "memory"); }
        else if (rem == 1) { asm volatile("cp.async.wait_group 1;\n" ::: "memory"); }
        else               { asm volatile("cp.async.wait_group 0;\n" ::: "memory"); }
        __syncthreads();

        {
            int s = it + NSTAGE - 1;
            if (s < iters) {
                int k = kbeg + s*32;
                int bufn = s & (NSTAGE-1);
                uint32_t sA = sbase + (uint32_t)bufn*STAGE_BYTES;
                uint32_t sB = sbase + (uint32_t)(NSTAGE + bufn)*STAGE_BYTES;
                cp16(sA + aoff0, Aq0 + k + c0, 16u);
                cp16(sA + aoff1, Aq1 + k + c1, 16u);
                cp16(sB + aoff0, Bq0 + k + c0, bv0 ? 16u : 0u);
                cp16(sB + aoff1, Bq1 + k + c1, bv1 ? 16u : 0u);
                asm volatile("cp.async.commit_group;\n" ::: "memory");
            }
        }

        int buf = it & (NSTAGE-1);
        uint32_t sAc = sbase + (uint32_t)buf*STAGE_BYTES;
        uint32_t sBc = sbase + (uint32_t)(NSTAGE + buf)*STAGE_BYTES;
#pragma unroll
        for (int kk = 0; kk < 2; kk++) {
            uint32_t afr[4][4], bfr[4][2];
#pragma unroll
            for (int mi = 0; mi < 4; mi++) {
                int row = wm*64 + mi*16 + ar;
                ldsm_x4(afr[mi], sAc + (uint32_t)(row*SSTRIDE + kk*16 + ak)*2);
            }
#pragma unroll
            for (int np = 0; np < 2; np++) {
                int row = wn*32 + np*16 + brr;
                uint32_t q4[4];
                ldsm_x4(q4, sBc + (uint32_t)(row*SSTRIDE + kk*16 + bk)*2);
                bfr[np*2+0][0]=q4[0]; bfr[np*2+0][1]=q4[1];
                bfr[np*2+1][0]=q4[2]; bfr[np*2+1][1]=q4[3];
            }
#pragma unroll
            for (int mi = 0; mi < 4; mi++)
#pragma unroll
                for (int ni = 0; ni < 4; ni++)
                    mma_fp16(acc[mi][ni], afr[mi], bfr[ni]);
        }
    }

    const int grp = lane >> 2, qd = lane & 3;
#pragma unroll
    for (int mi = 0; mi < 4; mi++) {
        int m = bm + wm*64 + mi*16 + grp;
#pragma unroll
        for (int ni = 0; ni < 4; ni++) {
            int n = bn + wn*32 + ni*8 + qd*2;
            if (n < N) {
                float c0v = acc[mi][ni][0], c1v = acc[mi][ni][1];
                float c2v = acc[mi][ni][2], c3v = acc[mi][ni][3];
                if (epi == 1) {
                    float b0 = bias[n], b1 = bias[n+1];
                    float x0 = c0v + b0, x1 = c1v + b1, x2 = c2v + b0, x3 = c3v + b1;
                    c0v = (x0 > 20.f) ? x0 : log1pf(__expf(x0));
                    c1v = (x1 > 20.f) ? x1 : log1pf(__expf(x1));
                    c2v = (x2 > 20.f) ? x2 : log1pf(__expf(x2));
                    c3v = (x3 > 20.f) ? x3 : log1pf(__expf(x3));
                }
                if (katomic) {
                    atomicAdd(&C[(size_t)m*ldc + n],       c0v);
                    if (n+1 < N) atomicAdd(&C[(size_t)m*ldc + n+1], c1v);
                    atomicAdd(&C[(size_t)(m+8)*ldc + n],   c2v);
                    if (n+1 < N) atomicAdd(&C[(size_t)(m+8)*ldc + n+1], c3v);
                } else {
                    *(float2*)(&C[(size_t)m*ldc + n])     = make_float2(c0v, c1v);
                    *(float2*)(&C[(size_t)(m+8)*ldc + n]) = make_float2(c2v, c3v);
                }
            }
        }
    }
}

// ------------------------------- driver --------------------------------------
extern "C" void kernel_launch(void* const* d_in, const int* in_sizes, int n_in,
                              void* d_out, int out_size)
{
    (void)in_sizes; (void)n_in; (void)out_size;
    const int*   ids   = (const int*)d_in[0];
    const int*   pos   = (const int*)d_in[1];
    const float* emb   = (const float*)d_in[2];
    const float* pemb  = (const float*)d_in[3];
    const float* normw = (const float*)d_in[4];
    const float* inw   = (const float*)d_in[5];
    const float* convw = (const float*)d_in[6];
    const float* convb = (const float*)d_in[7];
    const float* xpw   = (const float*)d_in[8];
    const float* dtw   = (const float*)d_in[9];
    const float* dtb   = (const float*)d_in[10];
    const float* Alog  = (const float*)d_in[11];
    const float* Dvec  = (const float*)d_in[12];
    const float* outw  = (const float*)d_in[13];
    const float* normf = (const float*)d_in[14];
    float* logits = (float*)d_out;

    static int attr_done = 0;
    if (!attr_done) {
        cudaFuncSetAttribute(gemm_mma, cudaFuncAttributeMaxDynamicSharedMemorySize, GEMM_SMEM);
        attr_done = 1;
    }

    float *hid, *res, *hs, *xz, *xc, *xd, *dtv, *Pv, *Sv, *hin;
    fp16 *hs16, *xc16, *y16, *xd16, *hsde16, *wb;
    cudaGetSymbolAddress((void**)&hid, g_hidden);
    cudaGetSymbolAddress((void**)&res, g_residual);
    cudaGetSymbolAddress((void**)&hs,  g_hs);
    cudaGetSymbolAddress((void**)&xz,  g_xz);
    cudaGetSymbolAddress((void**)&xc,  g_xconv);
    cudaGetSymbolAddress((void**)&xd,  g_xdbl);
    cudaGetSymbolAddress((void**)&dtv, g_dt);
    cudaGetSymbolAddress((void**)&Pv,  g_P);
    cudaGetSymbolAddress((void**)&Sv,  g_S);
    cudaGetSymbolAddress((void**)&hin, g_hin);
    cudaGetSymbolAddress((void**)&hs16,   g_hs16);
    cudaGetSymbolAddress((void**)&xc16,   g_xc16);
    cudaGetSymbolAddress((void**)&y16,    g_y16);
    cudaGetSymbolAddress((void**)&xd16,   g_xd16);
    cudaGetSymbolAddress((void**)&hsde16, g_hsde16);
    cudaGetSymbolAddress((void**)&wb,     g_wb16);

    embed_kernel<<<(TOK*DM + 255)/256, 256>>>(ids, pos, emb, pemb, hid, res);

    for (int layer = 0; layer < NL; layer++) {
        addnorm_kernel<<<TOK, 256>>>(hid, res, normw + (size_t)layer*DM, hs, hs16);

        // xz = hs @ in_proj^T : N=3072, K=768
        cvt_kernel<<<(2*DI*DM + 255)/256, 256>>>(inw + (size_t)layer*2*DI*DM, DM, DM, 2*DI*DM, wb);
        { dim3 g(TOK/128, 2*DI/128, 1);
          gemm_mma<<<g, 256, GEMM_SMEM>>>(hs16, wb, xz, 2*DI, DM, 2*DI, 0, 0, nullptr); }

        conv_silu_kernel<<<(TOK*DI + 255)/256, 256>>>(
            xz, convw + (size_t)layer*DI*4, convb + (size_t)layer*DI, xc, xc16);

        // x_dbl = xc @ x_proj^T : N=80, K=1536, split-K=8
        cvt_kernel<<<(XD*DI + 255)/256, 256>>>(xpw + (size_t)layer*XD*DI, DI, DI, XD*DI, wb);
        zero_kernel<<<(TOK*XD + 255)/256, 256>>>(xd, TOK*XD);
        { dim3 g(TOK/128, 1, 8);
          gemm_mma<<<g, 256, GEMM_SMEM>>>(xc16, wb, xd, XD, DI, XD, 1, 0, nullptr); }

        // dt = softplus(x_dbl[:, :48] @ dt_proj^T + dtb) : K padded 48->64
        cvt_pad_kernel<<<(TOK*DTK + 255)/256, 256>>>(xd, XD, DTR, DTK, TOK*DTK, xd16);
        cvt_pad_kernel<<<(DI*DTK + 255)/256, 256>>>(dtw + (size_t)layer*DI*DTR, DTR, DTR, DTK, DI*DTK, wb);
        { dim3 g(TOK/128, DI/128, 1);
          gemm_mma<<<g, 256, GEMM_SMEM>>>(xd16, wb, dtv, DI, DTK, DI, 0, 1, dtb + (size_t)layer*DI); }

        // chunked selective scan (register-state)
        scanA_kernel<<<(BB*CH*DI)/256, 256>>>(xc, dtv, xd, Alog + (size_t)layer*DI*DS, Pv, Sv);
        scanB_kernel<<<(BB*DI*DS + 255)/256, 256>>>(Pv, Sv, hin);
        scanC_kernel<<<(BB*CH*DI)/256, 256>>>(xc, dtv, xd, xz,
                                              Alog + (size_t)layer*DI*DS,
                                              Dvec + (size_t)layer*DI, hin, y16);

        // hid = y @ out_proj^T : N=768, K=1536, split-K=3
        cvt_kernel<<<(DM*DI + 255)/256, 256>>>(outw + (size_t)layer*DM*DI, DI, DI, DM*DI, wb);
        zero_kernel<<<(TOK*DM + 255)/256, 256>>>(hid, TOK*DM);
        { dim3 g(TOK/128, DM/128, 3);
          gemm_mma<<<g, 256, GEMM_SMEM>>>(y16, wb, hid, DM, DI, DM, 1, 0, nullptr); }
    }

    addnorm_kernel<<<TOK, 256>>>(hid, res, normf, hs, hs16);

    // logits = hs[:, :384] @ emb^T : N=32000, K=384
    cvt_kernel<<<(TOK*DE + 255)/256, 256>>>(hs, DM, DE, TOK*DE, hsde16);
    cvt_kernel<<<(VOCAB_N*DE + 255)/256, 256>>>(emb, DE, DE, VOCAB_N*DE, wb);
    { dim3 g(TOK/128, VOCAB_N/128, 1);
      gemm_mma<<<g, 256, GEMM_SMEM>>>(hsde16, wb, logits, VOCAB_N, DE, VOCAB_N, 0, 0, nullptr); }
}

// round 10
// speedup vs baseline: 2.4418x; 1.0495x over previous
#include <cuda_runtime.h>
#include <cuda_fp16.h>
#include <cstdint>

#define BB 2
#define LL 1024
#define DM 768
#define DI 1536
#define DS 16
#define DTR 48
#define XD 80            // DT_RANK + 2*D_STATE
#define NL 6
#define VOCAB_N 32000
#define DE 384
#define TOK (BB*LL)      // 2048
#define CH 32            // scan chunks
#define CLEN 32          // steps per chunk (LL/CH)
#define DTK 64           // padded K for dt projection (48 -> 64)
#define XSPLIT 8         // x_proj split-K
#define OSPLIT 3         // out_proj split-K

typedef __half fp16;

// ------------------------- scratch (no allocation allowed) -------------------
__device__ __align__(128) float g_hp0[TOK*DM];       // out_proj partial 0 / embed out
__device__ __align__(128) float g_hp1[TOK*DM];
__device__ __align__(128) float g_hp2[TOK*DM];
__device__ __align__(128) float g_residual[TOK*DM];
__device__ __align__(128) float g_hs[TOK*DM];
__device__ __align__(128) float g_xz[TOK*2*DI];
__device__ __align__(128) float g_xconv[TOK*DI];
__device__ __align__(128) float g_xdbl[TOK*XD];
__device__ __align__(128) float g_xdp[XSPLIT*TOK*XD];   // x_proj partials
__device__ __align__(128) float g_dt[TOK*DI];
__device__ __align__(128) float g_P[BB*DI*CH*DS];
__device__ __align__(128) float g_S[BB*DI*CH*DS];
__device__ __align__(128) float g_hin[BB*DI*CH*DS];
__device__ __align__(128) fp16  g_hs16[TOK*DM];
__device__ __align__(128) fp16  g_xc16[TOK*DI];
__device__ __align__(128) fp16  g_y16[TOK*DI];
__device__ __align__(128) fp16  g_xd16[TOK*DTK];
__device__ __align__(128) fp16  g_hsde16[TOK*DE];
// persistent fp16 weights (converted once per call, at graph start)
__device__ __align__(128) fp16  g_win16[NL*2*DI*DM];
__device__ __align__(128) fp16  g_wxp16[NL*XD*DI];
__device__ __align__(128) fp16  g_wdt16[NL*DI*DTK];
__device__ __align__(128) fp16  g_wout16[NL*DM*DI];
__device__ __align__(128) fp16  g_wemb16[VOCAB_N*DE];

// ------------------------- embed ---------------------------------------------
__global__ void embed_kernel(const int* __restrict__ ids, const int* __restrict__ pos,
                             const float* __restrict__ emb, const float* __restrict__ pemb,
                             float* __restrict__ hp0, float* __restrict__ hp1,
                             float* __restrict__ hp2, float* __restrict__ res)
{
    int idx = blockIdx.x * blockDim.x + threadIdx.x;
    if (idx >= TOK*DM) return;
    int t = idx / DM, c = idx % DM;
    float v;
    if (c < DE) v = emb[(size_t)ids[t]*DE + c];
    else        v = pemb[(size_t)pos[t]*DE + (c-DE)];
    hp0[idx] = v;
    hp1[idx] = 0.f;
    hp2[idx] = 0.f;
    res[idx] = 0.f;
}

// ----------- fp32 -> fp16 conversions ----------------------------------------
__global__ void cvt_kernel(const float* __restrict__ src, int lda, int K, int total,
                           fp16* __restrict__ dst)
{
    int idx = blockIdx.x * blockDim.x + threadIdx.x;
    if (idx >= total) return;
    int m = idx / K, k = idx - m*K;
    dst[(size_t)m*K + k] = __float2half(src[(size_t)m*lda + k]);
}
__global__ void cvt_pad_kernel(const float* __restrict__ src, int lda, int Kin, int Kout,
                               int total, fp16* __restrict__ dst)
{
    int idx = blockIdx.x * blockDim.x + threadIdx.x;
    if (idx >= total) return;
    int m = idx / Kout, k = idx - m*Kout;
    float v = (k < Kin) ? src[(size_t)m*lda + k] : 0.f;
    dst[(size_t)m*Kout + k] = __float2half(v);
}

// ---- sum x_proj partials -> xd fp32 ; also produce padded fp16 dt input -----
__global__ void sumxd_kernel(const float* __restrict__ xdp,
                             float* __restrict__ xd, fp16* __restrict__ xd16)
{
    int idx = blockIdx.x * blockDim.x + threadIdx.x;
    if (idx >= TOK*XD) return;
    int m = idx / XD, k = idx - m*XD;
    float s = 0.f;
#pragma unroll
    for (int p = 0; p < XSPLIT; p++) s += xdp[(size_t)p*TOK*XD + idx];
    xd[idx] = s;
    if (k < DTR)          xd16[(size_t)m*DTK + k] = __float2half(s);
    else if (k < DTR+16)  xd16[(size_t)m*DTK + k] = __float2half(0.f);  // pads 48..63
}

// ---- fused: res += sum(partials) ; out = rmsnorm(res)*w ; + fp16 output -----
__global__ __launch_bounds__(256) void addnorm_kernel(
    const float* __restrict__ h0, const float* __restrict__ h1,
    const float* __restrict__ h2, float* __restrict__ res,
    const float* __restrict__ w, float* __restrict__ out, fp16* __restrict__ outs)
{
    int t = blockIdx.x;
    const float* hp0 = h0 + (size_t)t*DM;
    const float* hp1 = h1 + (size_t)t*DM;
    const float* hp2 = h2 + (size_t)t*DM;
    float* rp = res + (size_t)t*DM;
    float v[3];
    float ss = 0.f;
#pragma unroll
    for (int q = 0; q < 3; q++) {
        int i = threadIdx.x + q*256;
        v[q] = hp0[i] + hp1[i] + hp2[i] + rp[i];
        ss += v[q]*v[q];
    }
#pragma unroll
    for (int o = 16; o > 0; o >>= 1) ss += __shfl_xor_sync(0xffffffffu, ss, o);
    __shared__ float red[8];
    if ((threadIdx.x & 31) == 0) red[threadIdx.x >> 5] = ss;
    __syncthreads();
    float tot = 0.f;
#pragma unroll
    for (int q = 0; q < 8; q++) tot += red[q];
    float rstd = rsqrtf(tot * (1.f/(float)DM) + 1e-5f);
#pragma unroll
    for (int q = 0; q < 3; q++) {
        int i = threadIdx.x + q*256;
        rp[i] = v[q];
        float u = v[q] * rstd * w[i];
        out[(size_t)t*DM + i] = u;
        outs[(size_t)t*DM + i] = __float2half(u);
    }
}

// ---- depthwise causal conv (width 4) + bias + silu (+fp16 output) ----------
__global__ void conv_silu_kernel(const float* __restrict__ xz,
                                 const float* __restrict__ cw,
                                 const float* __restrict__ cb,
                                 float* __restrict__ out, fp16* __restrict__ outs)
{
    int idx = blockIdx.x * blockDim.x + threadIdx.x;
    if (idx >= TOK*DI) return;
    int d = idx % DI;
    int t = idx / DI;
    int l = t % LL;
    float acc = cb[d];
    const float* base = xz + (size_t)t*(2*DI) + d;
#pragma unroll
    for (int j = 0; j < 4; j++) {
        int ll = l - 3 + j;
        if (ll >= 0) acc += cw[d*4+j] * base[(j-3)*(2*DI)];
    }
    float v = acc / (1.f + __expf(-acc));
    out[idx] = v;
    outs[idx] = __float2half(v);
}

// ---------------- chunked selective scan (register-state) --------------------
__device__ __forceinline__ void build_powers(float r, float* pw)
{
    pw[0] = r;
#pragma unroll
    for (int n = 1; n < DS; n++) {
        int m = n + 1;
        pw[n] = pw[m/2 - 1] * pw[(m - m/2) - 1];
    }
}

__global__ __launch_bounds__(256) void scanA_kernel(
    const float* __restrict__ xc, const float* __restrict__ dt,
    const float* __restrict__ xd, const float* __restrict__ A_log,
    float* __restrict__ Pv, float* __restrict__ Sv)
{
    int g = blockIdx.x * 256 + threadIdx.x;     // ((b*CH + c)*DI + d)
    int d = g % DI;
    int bc = g / DI;
    int c = bc % CH;
    int b = bc / CH;
    float A[DS];
    bool fast = true;
#pragma unroll
    for (int n = 0; n < DS; n++) A[n] = -__expf(A_log[d*DS + n]);
    float A1 = A[0];
#pragma unroll
    for (int n = 0; n < DS; n++)
        fast = fast && (fabsf(A[n] - (float)(n+1)*A1) <= 1e-4f*fabsf(A[n]));

    int l0 = c * CLEN;
    const float* xcb = xc + ((size_t)b*LL + l0)*DI + d;
    const float* dtb = dt + ((size_t)b*LL + l0)*DI + d;
    const float* xdb = xd + ((size_t)b*LL + l0)*XD + DTR;

    float h[DS];
#pragma unroll
    for (int n = 0; n < DS; n++) h[n] = 0.f;

    if (fast) {
        float rp = 1.f;
        for (int i = 0; i < CLEN; i++) {
            float xv  = xcb[(size_t)i*DI];
            float dtv = dtb[(size_t)i*DI];
            float Bv[DS];
#pragma unroll
            for (int q = 0; q < 4; q++)
                *(float4*)(Bv + q*4) = *(const float4*)(xdb + (size_t)i*XD + q*4);
            float w = dtv * xv;
            float r = __expf(dtv * A1);
            rp *= r;
            float pw[DS];
            build_powers(r, pw);
#pragma unroll
            for (int n = 0; n < DS; n++) h[n] = pw[n]*h[n] + w*Bv[n];
        }
        float pp[DS];
        build_powers(rp, pp);
#pragma unroll
        for (int q = 0; q < 4; q++) {
            *(float4*)&Pv[(size_t)g*DS + q*4] = *(float4*)(pp + q*4);
            *(float4*)&Sv[(size_t)g*DS + q*4] = *(float4*)(h + q*4);
        }
    } else {
        float P[DS];
#pragma unroll
        for (int n = 0; n < DS; n++) P[n] = 1.f;
        for (int i = 0; i < CLEN; i++) {
            float xv  = xcb[(size_t)i*DI];
            float dtv = dtb[(size_t)i*DI];
            float Bv[DS];
#pragma unroll
            for (int q = 0; q < 4; q++)
                *(float4*)(Bv + q*4) = *(const float4*)(xdb + (size_t)i*XD + q*4);
            float w = dtv * xv;
#pragma unroll
            for (int n = 0; n < DS; n++) {
                float dA = __expf(dtv * A[n]);
                P[n] *= dA;
                h[n] = dA*h[n] + w*Bv[n];
            }
        }
#pragma unroll
        for (int q = 0; q < 4; q++) {
            *(float4*)&Pv[(size_t)g*DS + q*4] = *(float4*)(P + q*4);
            *(float4*)&Sv[(size_t)g*DS + q*4] = *(float4*)(h + q*4);
        }
    }
}

__global__ void scanB_kernel(const float* __restrict__ Pv, const float* __restrict__ Sv,
                             float* __restrict__ hin)
{
    int g = blockIdx.x * blockDim.x + threadIdx.x;
    if (g >= BB*DI*DS) return;
    int n = g % DS;
    int pd = g / DS;
    int d = pd % DI;
    int b = pd / DI;
    float h = 0.f;
#pragma unroll
    for (int c = 0; c < CH; c++) {
        size_t idx = ((size_t)(b*CH + c)*DI + d)*DS + n;
        hin[idx] = h;
        h = Pv[idx]*h + Sv[idx];
    }
}

__global__ __launch_bounds__(256) void scanC_kernel(
    const float* __restrict__ xc, const float* __restrict__ dt,
    const float* __restrict__ xd, const float* __restrict__ xz,
    const float* __restrict__ A_log, const float* __restrict__ Dv,
    const float* __restrict__ hin, fp16* __restrict__ ys)
{
    int g = blockIdx.x * 256 + threadIdx.x;
    int d = g % DI;
    int bc = g / DI;
    int c = bc % CH;
    int b = bc / CH;
    float A[DS];
    bool fast = true;
#pragma unroll
    for (int n = 0; n < DS; n++) A[n] = -__expf(A_log[d*DS + n]);
    float A1 = A[0];
#pragma unroll
    for (int n = 0; n < DS; n++)
        fast = fast && (fabsf(A[n] - (float)(n+1)*A1) <= 1e-4f*fabsf(A[n]));
    float Dval = Dv[d];

    int l0 = c * CLEN;
    const float* xcb = xc + ((size_t)b*LL + l0)*DI + d;
    const float* dtb = dt + ((size_t)b*LL + l0)*DI + d;
    const float* xdb = xd + ((size_t)b*LL + l0)*XD + DTR;
    const float* xzb = xz + ((size_t)b*LL + l0)*(2*DI) + DI + d;
    fp16* yb = ys + ((size_t)b*LL + l0)*DI + d;

    float h[DS];
#pragma unroll
    for (int q = 0; q < 4; q++)
        *(float4*)(h + q*4) = *(const float4*)&hin[(size_t)g*DS + q*4];

    for (int i = 0; i < CLEN; i++) {
        float xv  = xcb[(size_t)i*DI];
        float dtv = dtb[(size_t)i*DI];
        float Bv[DS], Cv[DS];
#pragma unroll
        for (int q = 0; q < 4; q++) {
            *(float4*)(Bv + q*4) = *(const float4*)(xdb + (size_t)i*XD + q*4);
            *(float4*)(Cv + q*4) = *(const float4*)(xdb + (size_t)i*XD + DS + q*4);
        }
        float w = dtv * xv;
        float y = 0.f;
        if (fast) {
            float r = __expf(dtv * A1);
            float pw[DS];
            build_powers(r, pw);
#pragma unroll
            for (int n = 0; n < DS; n++) {
                h[n] = pw[n]*h[n] + w*Bv[n];
                y += h[n]*Cv[n];
            }
        } else {
#pragma unroll
            for (int n = 0; n < DS; n++) {
                float dA = __expf(dtv * A[n]);
                h[n] = dA*h[n] + w*Bv[n];
                y += h[n]*Cv[n];
            }
        }
        float z = xzb[(size_t)i*(2*DI)];
        float sig = 1.f / (1.f + __expf(-z));
        float v = (y + xv*Dval) * (z * sig);
        yb[(size_t)i*DI] = __float2half(v);
    }
}

// --------------------------- tensor-core GEMM (fp16) -------------------------
// C[m,n] = sum_k A[m,k]*B[n,k]. 128x128 block, BK=32, 4-stage cp.async pipeline.
// mode: 0 = direct store; 2 = per-z partial store at C + z*pstride. epi=1 softplus+bias.
__device__ __forceinline__ void ldsm_x4(uint32_t* r, uint32_t addr){
    asm volatile("ldmatrix.sync.aligned.m8n8.x4.shared.b16 {%0,%1,%2,%3}, [%4];"
      : "=r"(r[0]),"=r"(r[1]),"=r"(r[2]),"=r"(r[3]) : "r"(addr));
}
__device__ __forceinline__ void mma_fp16(float* c, const uint32_t* a, const uint32_t* b){
    asm volatile("mma.sync.aligned.m16n8k16.row.col.f32.f16.f16.f32 "
      "{%0,%1,%2,%3}, {%4,%5,%6,%7}, {%8,%9}, {%0,%1,%2,%3};"
      : "+f"(c[0]),"+f"(c[1]),"+f"(c[2]),"+f"(c[3])
      : "r"(a[0]),"r"(a[1]),"r"(a[2]),"r"(a[3]), "r"(b[0]),"r"(b[1]));
}
__device__ __forceinline__ void cp16(uint32_t daddr, const void* gptr, uint32_t srcsz){
    asm volatile("cp.async.cg.shared.global [%0], [%1], 16, %2;\n"
      :: "r"(daddr), "l"(gptr), "r"(srcsz));
}

#define SSTRIDE 40
#define STAGE_ELEM (128*SSTRIDE)
#define STAGE_BYTES (STAGE_ELEM*2)
#define NSTAGE 4
#define GEMM_SMEM (NSTAGE*2*STAGE_BYTES)   // 81920 B

__global__ __launch_bounds__(256,2) void gemm_mma(
    const fp16* __restrict__ A, const fp16* __restrict__ B,
    float* __restrict__ C, int N, int K2, int ldc,
    int mode, int pstride, int epi, const float* __restrict__ bias)
{
    extern __shared__ __align__(16) fp16 smem[];
    const int tid = threadIdx.x;
    const int lane = tid & 31, wid = tid >> 5;
    const int wm = wid & 1, wn = wid >> 1;
    const int bm = blockIdx.x * 128, bn = blockIdx.y * 128;

    const int ksplit = gridDim.z;
    const int per = (K2 / 32) / ksplit;
    const int kbeg = blockIdx.z * per * 32;
    const int iters = per;

    const int r0 = tid >> 2,            c0 = (tid & 3) * 8;
    const int r1 = (tid + 256) >> 2,    c1 = ((tid + 256) & 3) * 8;

    uint32_t sbase = (uint32_t)__cvta_generic_to_shared(smem);

    const int bw0 = bn + r0, bw1 = bn + r1;
    const bool bv0 = bw0 < N, bv1 = bw1 < N;
    const fp16* Bq0 = B + (size_t)(bv0 ? bw0 : 0)*K2;
    const fp16* Bq1 = B + (size_t)(bv1 ? bw1 : 0)*K2;
    const fp16* Aq0 = A + (size_t)(bm + r0)*K2;
    const fp16* Aq1 = A + (size_t)(bm + r1)*K2;

    const uint32_t aoff0 = (uint32_t)(r0*SSTRIDE + c0)*2;
    const uint32_t aoff1 = (uint32_t)(r1*SSTRIDE + c1)*2;

    float acc[4][4][4];
#pragma unroll
    for (int i = 0; i < 4; i++)
#pragma unroll
        for (int j = 0; j < 4; j++)
#pragma unroll
            for (int q = 0; q < 4; q++) acc[i][j][q] = 0.f;

#pragma unroll
    for (int s = 0; s < NSTAGE-1; s++) {
        if (s < iters) {
            int k = kbeg + s*32;
            uint32_t sA = sbase + (uint32_t)s*STAGE_BYTES;
            uint32_t sB = sbase + (uint32_t)(NSTAGE + s)*STAGE_BYTES;
            cp16(sA + aoff0, Aq0 + k + c0, 16u);
            cp16(sA + aoff1, Aq1 + k + c1, 16u);
            cp16(sB + aoff0, Bq0 + k + c0, bv0 ? 16u : 0u);
            cp16(sB + aoff1, Bq1 + k + c1, bv1 ? 16u : 0u);
        }
        asm volatile("cp.async.commit_group;\n" ::: "memory");
    }

    const int ar  = lane & 15;
    const int ak  = (lane >> 4) * 8;
    const int brr = (lane & 7) + ((lane >> 4) & 1)*8;
    const int bk  = ((lane >> 3) & 1) * 8;

    for (int it = 0; it < iters; it++) {
        int rem = iters - 1 - it;
        if (rem >= 2)      { asm volatile("cp.async.wait_group 2;\n" ::: "memory"); }
        else if (rem == 1) { asm volatile("cp.async.wait_group 1;\n" ::: "memory"); }
        else               { asm volatile("cp.async.wait_group 0;\n" ::: "memory"); }
        __syncthreads();

        {
            int s = it + NSTAGE - 1;
            if (s < iters) {
                int k = kbeg + s*32;
                int bufn = s & (NSTAGE-1);
                uint32_t sA = sbase + (uint32_t)bufn*STAGE_BYTES;
                uint32_t sB = sbase + (uint32_t)(NSTAGE + bufn)*STAGE_BYTES;
                cp16(sA + aoff0, Aq0 + k + c0, 16u);
                cp16(sA + aoff1, Aq1 + k + c1, 16u);
                cp16(sB + aoff0, Bq0 + k + c0, bv0 ? 16u : 0u);
                cp16(sB + aoff1, Bq1 + k + c1, bv1 ? 16u : 0u);
                asm volatile("cp.async.commit_group;\n" ::: "memory");
            }
        }

        int buf = it & (NSTAGE-1);
        uint32_t sAc = sbase + (uint32_t)buf*STAGE_BYTES;
        uint32_t sBc = sbase + (uint32_t)(NSTAGE + buf)*STAGE_BYTES;
#pragma unroll
        for (int kk = 0; kk < 2; kk++) {
            uint32_t afr[4][4], bfr[4][2];
#pragma unroll
            for (int mi = 0; mi < 4; mi++) {
                int row = wm*64 + mi*16 + ar;
                ldsm_x4(afr[mi], sAc + (uint32_t)(row*SSTRIDE + kk*16 + ak)*2);
            }
#pragma unroll
            for (int np = 0; np < 2; np++) {
                int row = wn*32 + np*16 + brr;
                uint32_t q4[4];
                ldsm_x4(q4, sBc + (uint32_t)(row*SSTRIDE + kk*16 + bk)*2);
                bfr[np*2+0][0]=q4[0]; bfr[np*2+0][1]=q4[1];
                bfr[np*2+1][0]=q4[2]; bfr[np*2+1][1]=q4[3];
            }
#pragma unroll
            for (int mi = 0; mi < 4; mi++)
#pragma unroll
                for (int ni = 0; ni < 4; ni++)
                    mma_fp16(acc[mi][ni], afr[mi], bfr[ni]);
        }
    }

    float* Cb = (mode == 2) ? (C + (size_t)blockIdx.z * pstride) : C;

    const int grp = lane >> 2, qd = lane & 3;
#pragma unroll
    for (int mi = 0; mi < 4; mi++) {
        int m = bm + wm*64 + mi*16 + grp;
#pragma unroll
        for (int ni = 0; ni < 4; ni++) {
            int n = bn + wn*32 + ni*8 + qd*2;
            if (n < N) {
                float c0v = acc[mi][ni][0], c1v = acc[mi][ni][1];
                float c2v = acc[mi][ni][2], c3v = acc[mi][ni][3];
                if (epi == 1) {
                    float b0 = bias[n], b1 = bias[n+1];
                    float x0 = c0v + b0, x1 = c1v + b1, x2 = c2v + b0, x3 = c3v + b1;
                    c0v = (x0 > 20.f) ? x0 : log1pf(__expf(x0));
                    c1v = (x1 > 20.f) ? x1 : log1pf(__expf(x1));
                    c2v = (x2 > 20.f) ? x2 : log1pf(__expf(x2));
                    c3v = (x3 > 20.f) ? x3 : log1pf(__expf(x3));
                }
                *(float2*)(&Cb[(size_t)m*ldc + n])     = make_float2(c0v, c1v);
                *(float2*)(&Cb[(size_t)(m+8)*ldc + n]) = make_float2(c2v, c3v);
            }
        }
    }
}

// ------------------------------- driver --------------------------------------
extern "C" void kernel_launch(void* const* d_in, const int* in_sizes, int n_in,
                              void* d_out, int out_size)
{
    (void)in_sizes; (void)n_in; (void)out_size;
    const int*   ids   = (const int*)d_in[0];
    const int*   pos   = (const int*)d_in[1];
    const float* emb   = (const float*)d_in[2];
    const float* pemb  = (const float*)d_in[3];
    const float* normw = (const float*)d_in[4];
    const float* inw   = (const float*)d_in[5];
    const float* convw = (const float*)d_in[6];
    const float* convb = (const float*)d_in[7];
    const float* xpw   = (const float*)d_in[8];
    const float* dtw   = (const float*)d_in[9];
    const float* dtb   = (const float*)d_in[10];
    const float* Alog  = (const float*)d_in[11];
    const float* Dvec  = (const float*)d_in[12];
    const float* outw  = (const float*)d_in[13];
    const float* normf = (const float*)d_in[14];
    float* logits = (float*)d_out;

    static int attr_done = 0;
    if (!attr_done) {
        cudaFuncSetAttribute(gemm_mma, cudaFuncAttributeMaxDynamicSharedMemorySize, GEMM_SMEM);
        attr_done = 1;
    }

    float *hp0, *hp1, *hp2, *res, *hs, *xz, *xc, *xd, *xdp, *dtv, *Pv, *Sv, *hin;
    fp16 *hs16, *xc16, *y16, *xd16, *hsde16;
    fp16 *win16, *wxp16, *wdt16, *wout16, *wemb16;
    cudaGetSymbolAddress((void**)&hp0, g_hp0);
    cudaGetSymbolAddress((void**)&hp1, g_hp1);
    cudaGetSymbolAddress((void**)&hp2, g_hp2);
    cudaGetSymbolAddress((void**)&res, g_residual);
    cudaGetSymbolAddress((void**)&hs,  g_hs);
    cudaGetSymbolAddress((void**)&xz,  g_xz);
    cudaGetSymbolAddress((void**)&xc,  g_xconv);
    cudaGetSymbolAddress((void**)&xd,  g_xdbl);
    cudaGetSymbolAddress((void**)&xdp, g_xdp);
    cudaGetSymbolAddress((void**)&dtv, g_dt);
    cudaGetSymbolAddress((void**)&Pv,  g_P);
    cudaGetSymbolAddress((void**)&Sv,  g_S);
    cudaGetSymbolAddress((void**)&hin, g_hin);
    cudaGetSymbolAddress((void**)&hs16,   g_hs16);
    cudaGetSymbolAddress((void**)&xc16,   g_xc16);
    cudaGetSymbolAddress((void**)&y16,    g_y16);
    cudaGetSymbolAddress((void**)&xd16,   g_xd16);
    cudaGetSymbolAddress((void**)&hsde16, g_hsde16);
    cudaGetSymbolAddress((void**)&win16,  g_win16);
    cudaGetSymbolAddress((void**)&wxp16,  g_wxp16);
    cudaGetSymbolAddress((void**)&wdt16,  g_wdt16);
    cudaGetSymbolAddress((void**)&wout16, g_wout16);
    cudaGetSymbolAddress((void**)&wemb16, g_wemb16);

    // -------- one-shot weight conversions (all layers) --------
    cvt_kernel<<<(NL*2*DI*DM + 255)/256, 256>>>(inw, DM, DM, NL*2*DI*DM, win16);
    cvt_kernel<<<(NL*XD*DI + 255)/256, 256>>>(xpw, DI, DI, NL*XD*DI, wxp16);
    cvt_pad_kernel<<<(NL*DI*DTK + 255)/256, 256>>>(dtw, DTR, DTR, DTK, NL*DI*DTK, wdt16);
    cvt_kernel<<<(NL*DM*DI + 255)/256, 256>>>(outw, DI, DI, NL*DM*DI, wout16);
    cvt_kernel<<<(VOCAB_N*DE + 255)/256, 256>>>(emb, DE, DE, VOCAB_N*DE, wemb16);

    embed_kernel<<<(TOK*DM + 255)/256, 256>>>(ids, pos, emb, pemb, hp0, hp1, hp2, res);

    for (int layer = 0; layer < NL; layer++) {
        addnorm_kernel<<<TOK, 256>>>(hp0, hp1, hp2, res,
                                     normw + (size_t)layer*DM, hs, hs16);

        // xz = hs @ in_proj^T : N=3072, K=768
        { dim3 g(TOK/128, 2*DI/128, 1);
          gemm_mma<<<g, 256, GEMM_SMEM>>>(hs16, win16 + (size_t)layer*2*DI*DM,
                                          xz, 2*DI, DM, 2*DI, 0, 0, 0, nullptr); }

        conv_silu_kernel<<<(TOK*DI + 255)/256, 256>>>(
            xz, convw + (size_t)layer*DI*4, convb + (size_t)layer*DI, xc, xc16);

        // x_dbl partials: N=80, K=1536, split-K=8 -> 8 partial buffers
        { dim3 g(TOK/128, 1, XSPLIT);
          gemm_mma<<<g, 256, GEMM_SMEM>>>(xc16, wxp16 + (size_t)layer*XD*DI,
                                          xdp, XD, DI, XD, 2, TOK*XD, 0, nullptr); }
        sumxd_kernel<<<(TOK*XD + 255)/256, 256>>>(xdp, xd, xd16);

        // dt = softplus(x_dbl[:, :48] @ dt_proj^T + dtb) : K padded 48->64
        { dim3 g(TOK/128, DI/128, 1);
          gemm_mma<<<g, 256, GEMM_SMEM>>>(xd16, wdt16 + (size_t)layer*DI*DTK,
                                          dtv, DI, DTK, DI, 0, 0, 1, dtb + (size_t)layer*DI); }

        // chunked selective scan (register-state)
        scanA_kernel<<<(BB*CH*DI)/256, 256>>>(xc, dtv, xd, Alog + (size_t)layer*DI*DS, Pv, Sv);
        scanB_kernel<<<(BB*DI*DS + 255)/256, 256>>>(Pv, Sv, hin);
        scanC_kernel<<<(BB*CH*DI)/256, 256>>>(xc, dtv, xd, xz,
                                              Alog + (size_t)layer*DI*DS,
                                              Dvec + (size_t)layer*DI, hin, y16);

        // out_proj partials: N=768, K=1536, split-K=3 -> hp0/hp1/hp2
        { dim3 g(TOK/128, DM/128, OSPLIT);
          gemm_mma<<<g, 256, GEMM_SMEM>>>(y16, wout16 + (size_t)layer*DM*DI,
                                          hp0, DM, DI, DM, 2, TOK*DM, 0, nullptr); }
    }

    addnorm_kernel<<<TOK, 256>>>(hp0, hp1, hp2, res, normf, hs, hs16);

    // logits = hs[:, :384] @ emb^T : N=32000, K=384
    cvt_kernel<<<(TOK*DE + 255)/256, 256>>>(hs, DM, DE, TOK*DE, hsde16);
    { dim3 g(TOK/128, VOCAB_N/128, 1);
      gemm_mma<<<g, 256, GEMM_SMEM>>>(hsde16, wemb16, logits, VOCAB_N, DE, VOCAB_N,
                                      0, 0, 0, nullptr); }
}

// round 11
// speedup vs baseline: 2.6167x; 1.0716x over previous
#include <cuda_runtime.h>
#include <cuda_fp16.h>
#include <cstdint>

#define BB 2
#define LL 1024
#define DM 768
#define DI 1536
#define DS 16
#define DTR 48
#define XD 80            // DT_RANK + 2*D_STATE
#define NL 6
#define VOCAB_N 32000
#define DE 384
#define TOK (BB*LL)      // 2048
#define CH 32            // scan chunks
#define CLEN 32          // steps per chunk (LL/CH)
#define DTK 64           // padded K for dt projection (48 -> 64)
#define XSPLIT 8         // x_proj split-K
#define OSPLIT 3         // out_proj split-K

typedef __half fp16;

// ------------------------- scratch (no allocation allowed) -------------------
__device__ __align__(128) float g_hp0[TOK*DM];       // out_proj partial 0 / embed out
__device__ __align__(128) float g_hp1[TOK*DM];
__device__ __align__(128) float g_hp2[TOK*DM];
__device__ __align__(128) float g_residual[TOK*DM];
__device__ __align__(128) float g_xdbl[TOK*XD];
__device__ __align__(128) float g_xdp[XSPLIT*TOK*XD];   // x_proj partials
__device__ __align__(128) float g_P[BB*DI*CH*DS];
__device__ __align__(128) float g_S[BB*DI*CH*DS];
__device__ __align__(128) float g_hin[BB*DI*CH*DS];
__device__ __align__(128) fp16  g_xz16[TOK*2*DI];
__device__ __align__(128) fp16  g_dt16[TOK*DI];
__device__ __align__(128) fp16  g_hs16[TOK*DM];
__device__ __align__(128) fp16  g_xc16[TOK*DI];
__device__ __align__(128) fp16  g_y16[TOK*DI];
__device__ __align__(128) fp16  g_xd16[TOK*DTK];
// persistent fp16 weights (converted once per call, at graph start)
__device__ __align__(128) fp16  g_win16[NL*2*DI*DM];
__device__ __align__(128) fp16  g_wxp16[NL*XD*DI];
__device__ __align__(128) fp16  g_wdt16[NL*DI*DTK];
__device__ __align__(128) fp16  g_wout16[NL*DM*DI];
__device__ __align__(128) fp16  g_wemb16[VOCAB_N*DE];

// ------------------------- embed ---------------------------------------------
__global__ void embed_kernel(const int* __restrict__ ids, const int* __restrict__ pos,
                             const float* __restrict__ emb, const float* __restrict__ pemb,
                             float* __restrict__ hp0, float* __restrict__ hp1,
                             float* __restrict__ hp2, float* __restrict__ res)
{
    int idx = blockIdx.x * blockDim.x + threadIdx.x;
    if (idx >= TOK*DM) return;
    int t = idx / DM, c = idx % DM;
    float v;
    if (c < DE) v = emb[(size_t)ids[t]*DE + c];
    else        v = pemb[(size_t)pos[t]*DE + (c-DE)];
    hp0[idx] = v;
    hp1[idx] = 0.f;
    hp2[idx] = 0.f;
    res[idx] = 0.f;
}

// ----------- fp32 -> fp16 conversions ----------------------------------------
// flat vectorized: 8 elems per thread (requires total % 8 == 0)
__global__ void cvt_flat_kernel(const float* __restrict__ src, fp16* __restrict__ dst,
                                int total8)
{
    int i = blockIdx.x * blockDim.x + threadIdx.x;
    if (i >= total8) return;
    const float4* s = (const float4*)src + (size_t)i*2;
    float4 a = s[0], b = s[1];
    __half2 h0 = __floats2half2_rn(a.x, a.y);
    __half2 h1 = __floats2half2_rn(a.z, a.w);
    __half2 h2 = __floats2half2_rn(b.x, b.y);
    __half2 h3 = __floats2half2_rn(b.z, b.w);
    uint4 o;
    o.x = *reinterpret_cast<uint32_t*>(&h0);
    o.y = *reinterpret_cast<uint32_t*>(&h1);
    o.z = *reinterpret_cast<uint32_t*>(&h2);
    o.w = *reinterpret_cast<uint32_t*>(&h3);
    *((uint4*)dst + i) = o;
}
// padded: take Kin cols (stride lda), write rows stride Kout, zero-fill rest
__global__ void cvt_pad_kernel(const float* __restrict__ src, int lda, int Kin, int Kout,
                               int total, fp16* __restrict__ dst)
{
    int idx = blockIdx.x * blockDim.x + threadIdx.x;
    if (idx >= total) return;
    int m = idx / Kout, k = idx - m*Kout;
    float v = (k < Kin) ? src[(size_t)m*lda + k] : 0.f;
    dst[(size_t)m*Kout + k] = __float2half(v);
}

// ---- sum x_proj partials -> xd fp32 ; also produce padded fp16 dt input -----
__global__ void sumxd_kernel(const float* __restrict__ xdp,
                             float* __restrict__ xd, fp16* __restrict__ xd16)
{
    int idx = blockIdx.x * blockDim.x + threadIdx.x;
    if (idx >= TOK*XD) return;
    int m = idx / XD, k = idx - m*XD;
    float s = 0.f;
#pragma unroll
    for (int p = 0; p < XSPLIT; p++) s += xdp[(size_t)p*TOK*XD + idx];
    xd[idx] = s;
    if (k < DTR)          xd16[(size_t)m*DTK + k] = __float2half(s);
    else if (k < DTR+16)  xd16[(size_t)m*DTK + k] = __float2half(0.f);
}

// ---- fused: res += sum(partials) ; hs16 = fp16(rmsnorm(res)*w) --------------
__global__ __launch_bounds__(256) void addnorm_kernel(
    const float* __restrict__ h0, const float* __restrict__ h1,
    const float* __restrict__ h2, float* __restrict__ res,
    const float* __restrict__ w, fp16* __restrict__ outs)
{
    int t = blockIdx.x;
    const float* hp0 = h0 + (size_t)t*DM;
    const float* hp1 = h1 + (size_t)t*DM;
    const float* hp2 = h2 + (size_t)t*DM;
    float* rp = res + (size_t)t*DM;
    float v[3];
    float ss = 0.f;
#pragma unroll
    for (int q = 0; q < 3; q++) {
        int i = threadIdx.x + q*256;
        v[q] = hp0[i] + hp1[i] + hp2[i] + rp[i];
        ss += v[q]*v[q];
    }
#pragma unroll
    for (int o = 16; o > 0; o >>= 1) ss += __shfl_xor_sync(0xffffffffu, ss, o);
    __shared__ float red[8];
    if ((threadIdx.x & 31) == 0) red[threadIdx.x >> 5] = ss;
    __syncthreads();
    float tot = 0.f;
#pragma unroll
    for (int q = 0; q < 8; q++) tot += red[q];
    float rstd = rsqrtf(tot * (1.f/(float)DM) + 1e-5f);
#pragma unroll
    for (int q = 0; q < 3; q++) {
        int i = threadIdx.x + q*256;
        rp[i] = v[q];
        outs[(size_t)t*DM + i] = __float2half(v[q] * rstd * w[i]);
    }
}

// ---- depthwise causal conv (width 4, fp16 in) + bias + silu -> fp16 --------
__global__ void conv_silu_kernel(const fp16* __restrict__ xz,
                                 const float* __restrict__ cw,
                                 const float* __restrict__ cb,
                                 fp16* __restrict__ outs)
{
    int idx = blockIdx.x * blockDim.x + threadIdx.x;
    if (idx >= TOK*DI) return;
    int d = idx % DI;
    int t = idx / DI;
    int l = t % LL;
    float acc = cb[d];
    const fp16* base = xz + (size_t)t*(2*DI) + d;
#pragma unroll
    for (int j = 0; j < 4; j++) {
        int ll = l - 3 + j;
        if (ll >= 0) acc += cw[d*4+j] * __half2float(base[(ptrdiff_t)(j-3)*(2*DI)]);
    }
    float v = acc / (1.f + __expf(-acc));
    outs[idx] = __float2half(v);
}

// ---------------- chunked selective scan (register-state, fp16 inputs) -------
__device__ __forceinline__ void build_powers(float r, float* pw)
{
    pw[0] = r;
#pragma unroll
    for (int n = 1; n < DS; n++) {
        int m = n + 1;
        pw[n] = pw[m/2 - 1] * pw[(m - m/2) - 1];
    }
}

__global__ __launch_bounds__(256) void scanA_kernel(
    const fp16* __restrict__ xc, const fp16* __restrict__ dt,
    const float* __restrict__ xd, const float* __restrict__ A_log,
    float* __restrict__ Pv, float* __restrict__ Sv)
{
    int g = blockIdx.x * 256 + threadIdx.x;     // ((b*CH + c)*DI + d)
    int d = g % DI;
    int bc = g / DI;
    int c = bc % CH;
    int b = bc / CH;
    float A[DS];
    bool fast = true;
#pragma unroll
    for (int n = 0; n < DS; n++) A[n] = -__expf(A_log[d*DS + n]);
    float A1 = A[0];
#pragma unroll
    for (int n = 0; n < DS; n++)
        fast = fast && (fabsf(A[n] - (float)(n+1)*A1) <= 1e-4f*fabsf(A[n]));

    int l0 = c * CLEN;
    const fp16* xcb = xc + ((size_t)b*LL + l0)*DI + d;
    const fp16* dtb = dt + ((size_t)b*LL + l0)*DI + d;
    const float* xdb = xd + ((size_t)b*LL + l0)*XD + DTR;

    float h[DS];
#pragma unroll
    for (int n = 0; n < DS; n++) h[n] = 0.f;

    if (fast) {
        float rp = 1.f;
        for (int i = 0; i < CLEN; i++) {
            float xv  = __half2float(xcb[(size_t)i*DI]);
            float dtv = __half2float(dtb[(size_t)i*DI]);
            float Bv[DS];
#pragma unroll
            for (int q = 0; q < 4; q++)
                *(float4*)(Bv + q*4) = *(const float4*)(xdb + (size_t)i*XD + q*4);
            float w = dtv * xv;
            float r = __expf(dtv * A1);
            rp *= r;
            float pw[DS];
            build_powers(r, pw);
#pragma unroll
            for (int n = 0; n < DS; n++) h[n] = pw[n]*h[n] + w*Bv[n];
        }
        float pp[DS];
        build_powers(rp, pp);
#pragma unroll
        for (int q = 0; q < 4; q++) {
            *(float4*)&Pv[(size_t)g*DS + q*4] = *(float4*)(pp + q*4);
            *(float4*)&Sv[(size_t)g*DS + q*4] = *(float4*)(h + q*4);
        }
    } else {
        float P[DS];
#pragma unroll
        for (int n = 0; n < DS; n++) P[n] = 1.f;
        for (int i = 0; i < CLEN; i++) {
            float xv  = __half2float(xcb[(size_t)i*DI]);
            float dtv = __half2float(dtb[(size_t)i*DI]);
            float Bv[DS];
#pragma unroll
            for (int q = 0; q < 4; q++)
                *(float4*)(Bv + q*4) = *(const float4*)(xdb + (size_t)i*XD + q*4);
            float w = dtv * xv;
#pragma unroll
            for (int n = 0; n < DS; n++) {
                float dA = __expf(dtv * A[n]);
                P[n] *= dA;
                h[n] = dA*h[n] + w*Bv[n];
            }
        }
#pragma unroll
        for (int q = 0; q < 4; q++) {
            *(float4*)&Pv[(size_t)g*DS + q*4] = *(float4*)(P + q*4);
            *(float4*)&Sv[(size_t)g*DS + q*4] = *(float4*)(h + q*4);
        }
    }
}

__global__ void scanB_kernel(const float* __restrict__ Pv, const float* __restrict__ Sv,
                             float* __restrict__ hin)
{
    int g = blockIdx.x * blockDim.x + threadIdx.x;
    if (g >= BB*DI*DS) return;
    int n = g % DS;
    int pd = g / DS;
    int d = pd % DI;
    int b = pd / DI;
    float h = 0.f;
#pragma unroll
    for (int c = 0; c < CH; c++) {
        size_t idx = ((size_t)(b*CH + c)*DI + d)*DS + n;
        hin[idx] = h;
        h = Pv[idx]*h + Sv[idx];
    }
}

__global__ __launch_bounds__(256) void scanC_kernel(
    const fp16* __restrict__ xc, const fp16* __restrict__ dt,
    const float* __restrict__ xd, const fp16* __restrict__ xz,
    const float* __restrict__ A_log, const float* __restrict__ Dv,
    const float* __restrict__ hin, fp16* __restrict__ ys)
{
    int g = blockIdx.x * 256 + threadIdx.x;
    int d = g % DI;
    int bc = g / DI;
    int c = bc % CH;
    int b = bc / CH;
    float A[DS];
    bool fast = true;
#pragma unroll
    for (int n = 0; n < DS; n++) A[n] = -__expf(A_log[d*DS + n]);
    float A1 = A[0];
#pragma unroll
    for (int n = 0; n < DS; n++)
        fast = fast && (fabsf(A[n] - (float)(n+1)*A1) <= 1e-4f*fabsf(A[n]));
    float Dval = Dv[d];

    int l0 = c * CLEN;
    const fp16* xcb = xc + ((size_t)b*LL + l0)*DI + d;
    const fp16* dtb = dt + ((size_t)b*LL + l0)*DI + d;
    const float* xdb = xd + ((size_t)b*LL + l0)*XD + DTR;
    const fp16* xzb = xz + ((size_t)b*LL + l0)*(2*DI) + DI + d;
    fp16* yb = ys + ((size_t)b*LL + l0)*DI + d;

    float h[DS];
#pragma unroll
    for (int q = 0; q < 4; q++)
        *(float4*)(h + q*4) = *(const float4*)&hin[(size_t)g*DS + q*4];

    for (int i = 0; i < CLEN; i++) {
        float xv  = __half2float(xcb[(size_t)i*DI]);
        float dtv = __half2float(dtb[(size_t)i*DI]);
        float Bv[DS], Cv[DS];
#pragma unroll
        for (int q = 0; q < 4; q++) {
            *(float4*)(Bv + q*4) = *(const float4*)(xdb + (size_t)i*XD + q*4);
            *(float4*)(Cv + q*4) = *(const float4*)(xdb + (size_t)i*XD + DS + q*4);
        }
        float w = dtv * xv;
        float y = 0.f;
        if (fast) {
            float r = __expf(dtv * A1);
            float pw[DS];
            build_powers(r, pw);
#pragma unroll
            for (int n = 0; n < DS; n++) {
                h[n] = pw[n]*h[n] + w*Bv[n];
                y += h[n]*Cv[n];
            }
        } else {
#pragma unroll
            for (int n = 0; n < DS; n++) {
                float dA = __expf(dtv * A[n]);
                h[n] = dA*h[n] + w*Bv[n];
                y += h[n]*Cv[n];
            }
        }
        float z = __half2float(xzb[(size_t)i*(2*DI)]);
        float sig = 1.f / (1.f + __expf(-z));
        float v = (y + xv*Dval) * (z * sig);
        yb[(size_t)i*DI] = __float2half(v);
    }
}

// --------------------------- tensor-core GEMM (fp16) -------------------------
// C[m,n] = sum_k A[m,k]*B[n,k]. 128x128 block, BK=32, 4-stage cp.async pipeline.
// A row stride = lda (>= K2). mode: 0 direct; 2 per-z partial at C + z*pstride.
// epi=1: softplus(x+bias). outhalf: store fp16 (mode 0 only).
__device__ __forceinline__ void ldsm_x4(uint32_t* r, uint32_t addr){
    asm volatile("ldmatrix.sync.aligned.m8n8.x4.shared.b16 {%0,%1,%2,%3}, [%4];"
      : "=r"(r[0]),"=r"(r[1]),"=r"(r[2]),"=r"(r[3]) : "r"(addr));
}
__device__ __forceinline__ void mma_fp16(float* c, const uint32_t* a, const uint32_t* b){
    asm volatile("mma.sync.aligned.m16n8k16.row.col.f32.f16.f16.f32 "
      "{%0,%1,%2,%3}, {%4,%5,%6,%7}, {%8,%9}, {%0,%1,%2,%3};"
      : "+f"(c[0]),"+f"(c[1]),"+f"(c[2]),"+f"(c[3])
      : "r"(a[0]),"r"(a[1]),"r"(a[2]),"r"(a[3]), "r"(b[0]),"r"(b[1]));
}
__device__ __forceinline__ void cp16(uint32_t daddr, const void* gptr, uint32_t srcsz){
    asm volatile("cp.async.cg.shared.global [%0], [%1], 16, %2;\n"
      :: "r"(daddr), "l"(gptr), "r"(srcsz));
}

#define SSTRIDE 40
#define STAGE_ELEM (128*SSTRIDE)
#define STAGE_BYTES (STAGE_ELEM*2)
#define NSTAGE 4
#define GEMM_SMEM (NSTAGE*2*STAGE_BYTES)   // 81920 B

__global__ __launch_bounds__(256,2) void gemm_mma(
    const fp16* __restrict__ A, int lda, const fp16* __restrict__ B,
    void* __restrict__ Cv_, int N, int K2, int ldc,
    int mode, int pstride, int epi, const float* __restrict__ bias, int outhalf)
{
    extern __shared__ __align__(16) fp16 smem[];
    const int tid = threadIdx.x;
    const int lane = tid & 31, wid = tid >> 5;
    const int wm = wid & 1, wn = wid >> 1;
    const int bm = blockIdx.x * 128, bn = blockIdx.y * 128;

    const int ksplit = gridDim.z;
    const int per = (K2 / 32) / ksplit;
    const int kbeg = blockIdx.z * per * 32;
    const int iters = per;

    const int r0 = tid >> 2,            c0 = (tid & 3) * 8;
    const int r1 = (tid + 256) >> 2,    c1 = ((tid + 256) & 3) * 8;

    uint32_t sbase = (uint32_t)__cvta_generic_to_shared(smem);

    const int bw0 = bn + r0, bw1 = bn + r1;
    const bool bv0 = bw0 < N, bv1 = bw1 < N;
    const fp16* Bq0 = B + (size_t)(bv0 ? bw0 : 0)*K2;
    const fp16* Bq1 = B + (size_t)(bv1 ? bw1 : 0)*K2;
    const fp16* Aq0 = A + (size_t)(bm + r0)*lda;
    const fp16* Aq1 = A + (size_t)(bm + r1)*lda;

    const uint32_t aoff0 = (uint32_t)(r0*SSTRIDE + c0)*2;
    const uint32_t aoff1 = (uint32_t)(r1*SSTRIDE + c1)*2;

    float acc[4][4][4];
#pragma unroll
    for (int i = 0; i < 4; i++)
#pragma unroll
        for (int j = 0; j < 4; j++)
#pragma unroll
            for (int q = 0; q < 4; q++) acc[i][j][q] = 0.f;

#pragma unroll
    for (int s = 0; s < NSTAGE-1; s++) {
        if (s < iters) {
            int k = kbeg + s*32;
            uint32_t sA = sbase + (uint32_t)s*STAGE_BYTES;
            uint32_t sB = sbase + (uint32_t)(NSTAGE + s)*STAGE_BYTES;
            cp16(sA + aoff0, Aq0 + k + c0, 16u);
            cp16(sA + aoff1, Aq1 + k + c1, 16u);
            cp16(sB + aoff0, Bq0 + k + c0, bv0 ? 16u : 0u);
            cp16(sB + aoff1, Bq1 + k + c1, bv1 ? 16u : 0u);
        }
        asm volatile("cp.async.commit_group;\n" ::: "memory");
    }

    const int ar  = lane & 15;
    const int ak  = (lane >> 4) * 8;
    const int brr = (lane & 7) + ((lane >> 4) & 1)*8;
    const int bk  = ((lane >> 3) & 1) * 8;

    for (int it = 0; it < iters; it++) {
        int rem = iters - 1 - it;
        if (rem >= 2)      { asm volatile("cp.async.wait_group 2;\n" ::: "memory"); }
        else if (rem == 1) { asm volatile("cp.async.wait_group 1;\n" ::: "memory"); }
        else               { asm volatile("cp.async.wait_group 0;\n" ::: "memory"); }
        __syncthreads();

        {
            int s = it + NSTAGE - 1;
            if (s < iters) {
                int k = kbeg + s*32;
                int bufn = s & (NSTAGE-1);
                uint32_t sA = sbase + (uint32_t)bufn*STAGE_BYTES;
                uint32_t sB = sbase + (uint32_t)(NSTAGE + bufn)*STAGE_BYTES;
                cp16(sA + aoff0, Aq0 + k + c0, 16u);
                cp16(sA + aoff1, Aq1 + k + c1, 16u);
                cp16(sB + aoff0, Bq0 + k + c0, bv0 ? 16u : 0u);
                cp16(sB + aoff1, Bq1 + k + c1, bv1 ? 16u : 0u);
                asm volatile("cp.async.commit_group;\n" ::: "memory");
            }
        }

        int buf = it & (NSTAGE-1);
        uint32_t sAc = sbase + (uint32_t)buf*STAGE_BYTES;
        uint32_t sBc = sbase + (uint32_t)(NSTAGE + buf)*STAGE_BYTES;
#pragma unroll
        for (int kk = 0; kk < 2; kk++) {
            uint32_t afr[4][4], bfr[4][2];
#pragma unroll
            for (int mi = 0; mi < 4; mi++) {
                int row = wm*64 + mi*16 + ar;
                ldsm_x4(afr[mi], sAc + (uint32_t)(row*SSTRIDE + kk*16 + ak)*2);
            }
#pragma unroll
            for (int np = 0; np < 2; np++) {
                int row = wn*32 + np*16 + brr;
                uint32_t q4[4];
                ldsm_x4(q4, sBc + (uint32_t)(row*SSTRIDE + kk*16 + bk)*2);
                bfr[np*2+0][0]=q4[0]; bfr[np*2+0][1]=q4[1];
                bfr[np*2+1][0]=q4[2]; bfr[np*2+1][1]=q4[3];
            }
#pragma unroll
            for (int mi = 0; mi < 4; mi++)
#pragma unroll
                for (int ni = 0; ni < 4; ni++)
                    mma_fp16(acc[mi][ni], afr[mi], bfr[ni]);
        }
    }

    float* Cf = (float*)Cv_;
    if (mode == 2) Cf += (size_t)blockIdx.z * pstride;
    fp16* Ch = (fp16*)Cv_;

    const int grp = lane >> 2, qd = lane & 3;
#pragma unroll
    for (int mi = 0; mi < 4; mi++) {
        int m = bm + wm*64 + mi*16 + grp;
#pragma unroll
        for (int ni = 0; ni < 4; ni++) {
            int n = bn + wn*32 + ni*8 + qd*2;
            if (n < N) {
                float c0v = acc[mi][ni][0], c1v = acc[mi][ni][1];
                float c2v = acc[mi][ni][2], c3v = acc[mi][ni][3];
                if (epi == 1) {
                    float b0 = bias[n], b1 = bias[n+1];
                    float x0 = c0v + b0, x1 = c1v + b1, x2 = c2v + b0, x3 = c3v + b1;
                    c0v = (x0 > 20.f) ? x0 : log1pf(__expf(x0));
                    c1v = (x1 > 20.f) ? x1 : log1pf(__expf(x1));
                    c2v = (x2 > 20.f) ? x2 : log1pf(__expf(x2));
                    c3v = (x3 > 20.f) ? x3 : log1pf(__expf(x3));
                }
                if (outhalf) {
                    *(__half2*)(&Ch[(size_t)m*ldc + n])     = __floats2half2_rn(c0v, c1v);
                    *(__half2*)(&Ch[(size_t)(m+8)*ldc + n]) = __floats2half2_rn(c2v, c3v);
                } else {
                    *(float2*)(&Cf[(size_t)m*ldc + n])     = make_float2(c0v, c1v);
                    *(float2*)(&Cf[(size_t)(m+8)*ldc + n]) = make_float2(c2v, c3v);
                }
            }
        }
    }
}

// ------------------------------- driver --------------------------------------
extern "C" void kernel_launch(void* const* d_in, const int* in_sizes, int n_in,
                              void* d_out, int out_size)
{
    (void)in_sizes; (void)n_in; (void)out_size;
    const int*   ids   = (const int*)d_in[0];
    const int*   pos   = (const int*)d_in[1];
    const float* emb   = (const float*)d_in[2];
    const float* pemb  = (const float*)d_in[3];
    const float* normw = (const float*)d_in[4];
    const float* inw   = (const float*)d_in[5];
    const float* convw = (const float*)d_in[6];
    const float* convb = (const float*)d_in[7];
    const float* xpw   = (const float*)d_in[8];
    const float* dtw   = (const float*)d_in[9];
    const float* dtb   = (const float*)d_in[10];
    const float* Alog  = (const float*)d_in[11];
    const float* Dvec  = (const float*)d_in[12];
    const float* outw  = (const float*)d_in[13];
    const float* normf = (const float*)d_in[14];
    float* logits = (float*)d_out;

    static int attr_done = 0;
    if (!attr_done) {
        cudaFuncSetAttribute(gemm_mma, cudaFuncAttributeMaxDynamicSharedMemorySize, GEMM_SMEM);
        attr_done = 1;
    }

    float *hp0, *hp1, *hp2, *res, *xd, *xdp, *Pv, *Sv, *hin;
    fp16 *xz16, *dt16, *hs16, *xc16, *y16, *xd16;
    fp16 *win16, *wxp16, *wdt16, *wout16, *wemb16;
    cudaGetSymbolAddress((void**)&hp0, g_hp0);
    cudaGetSymbolAddress((void**)&hp1, g_hp1);
    cudaGetSymbolAddress((void**)&hp2, g_hp2);
    cudaGetSymbolAddress((void**)&res, g_residual);
    cudaGetSymbolAddress((void**)&xd,  g_xdbl);
    cudaGetSymbolAddress((void**)&xdp, g_xdp);
    cudaGetSymbolAddress((void**)&Pv,  g_P);
    cudaGetSymbolAddress((void**)&Sv,  g_S);
    cudaGetSymbolAddress((void**)&hin, g_hin);
    cudaGetSymbolAddress((void**)&xz16, g_xz16);
    cudaGetSymbolAddress((void**)&dt16, g_dt16);
    cudaGetSymbolAddress((void**)&hs16, g_hs16);
    cudaGetSymbolAddress((void**)&xc16, g_xc16);
    cudaGetSymbolAddress((void**)&y16,  g_y16);
    cudaGetSymbolAddress((void**)&xd16, g_xd16);
    cudaGetSymbolAddress((void**)&win16,  g_win16);
    cudaGetSymbolAddress((void**)&wxp16,  g_wxp16);
    cudaGetSymbolAddress((void**)&wdt16,  g_wdt16);
    cudaGetSymbolAddress((void**)&wout16, g_wout16);
    cudaGetSymbolAddress((void**)&wemb16, g_wemb16);

    // -------- one-shot weight conversions (all layers, vectorized) --------
    cvt_flat_kernel<<<(NL*2*DI*DM/8 + 255)/256, 256>>>(inw, win16, NL*2*DI*DM/8);
    cvt_flat_kernel<<<(NL*XD*DI/8 + 255)/256, 256>>>(xpw, wxp16, NL*XD*DI/8);
    cvt_pad_kernel<<<(NL*DI*DTK + 255)/256, 256>>>(dtw, DTR, DTR, DTK, NL*DI*DTK, wdt16);
    cvt_flat_kernel<<<(NL*DM*DI/8 + 255)/256, 256>>>(outw, wout16, NL*DM*DI/8);
    cvt_flat_kernel<<<(VOCAB_N*DE/8 + 255)/256, 256>>>(emb, wemb16, VOCAB_N*DE/8);

    embed_kernel<<<(TOK*DM + 255)/256, 256>>>(ids, pos, emb, pemb, hp0, hp1, hp2, res);

    for (int layer = 0; layer < NL; layer++) {
        addnorm_kernel<<<TOK, 256>>>(hp0, hp1, hp2, res,
                                     normw + (size_t)layer*DM, hs16);

        // xz16 = fp16(hs @ in_proj^T) : N=3072, K=768
        { dim3 g(TOK/128, 2*DI/128, 1);
          gemm_mma<<<g, 256, GEMM_SMEM>>>(hs16, DM, win16 + (size_t)layer*2*DI*DM,
                                          xz16, 2*DI, DM, 2*DI, 0, 0, 0, nullptr, 1); }

        conv_silu_kernel<<<(TOK*DI + 255)/256, 256>>>(
            xz16, convw + (size_t)layer*DI*4, convb + (size_t)layer*DI, xc16);

        // x_dbl partials: N=80, K=1536, split-K=8 -> 8 fp32 partial buffers
        { dim3 g(TOK/128, 1, XSPLIT);
          gemm_mma<<<g, 256, GEMM_SMEM>>>(xc16, DI, wxp16 + (size_t)layer*XD*DI,
                                          xdp, XD, DI, XD, 2, TOK*XD, 0, nullptr, 0); }
        sumxd_kernel<<<(TOK*XD + 255)/256, 256>>>(xdp, xd, xd16);

        // dt16 = fp16(softplus(x_dbl[:, :48] @ dt_proj^T + dtb)) : K padded 64
        { dim3 g(TOK/128, DI/128, 1);
          gemm_mma<<<g, 256, GEMM_SMEM>>>(xd16, DTK, wdt16 + (size_t)layer*DI*DTK,
                                          dt16, DI, DTK, DI, 0, 0, 1,
                                          dtb + (size_t)layer*DI, 1); }

        // chunked selective scan (register-state)
        scanA_kernel<<<(BB*CH*DI)/256, 256>>>(xc16, dt16, xd,
                                              Alog + (size_t)layer*DI*DS, Pv, Sv);
        scanB_kernel<<<(BB*DI*DS + 255)/256, 256>>>(Pv, Sv, hin);
        scanC_kernel<<<(BB*CH*DI)/256, 256>>>(xc16, dt16, xd, xz16,
                                              Alog + (size_t)layer*DI*DS,
                                              Dvec + (size_t)layer*DI, hin, y16);

        // out_proj partials: N=768, K=1536, split-K=3 -> hp0/hp1/hp2 (contiguous)
        { dim3 g(TOK/128, DM/128, OSPLIT);
          gemm_mma<<<g, 256, GEMM_SMEM>>>(y16, DI, wout16 + (size_t)layer*DM*DI,
                                          hp0, DM, DI, DM, 2, TOK*DM, 0, nullptr, 0); }
    }

    addnorm_kernel<<<TOK, 256>>>(hp0, hp1, hp2, res, normf, hs16);

    // logits = hs16[:, :384] @ emb^T : N=32000, K=384 (A stride = DM)
    { dim3 g(TOK/128, VOCAB_N/128, 1);
      gemm_mma<<<g, 256, GEMM_SMEM>>>(hs16, DM, wemb16, logits, VOCAB_N, DE, VOCAB_N,
                                      0, 0, 0, nullptr, 0); }
}